// round 13
// baseline (speedup 1.0000x reference)
#include <cuda_runtime.h>
#include <cuda_bf16.h>
#include <cstdint>

#define B_   8
#define L_   4096
#define C_   1024
#define D_   1024
#define NS   256
#define MLPD 512
#define TIT  6
#define LNEPS 1e-5f

typedef unsigned long long u64;
typedef __nv_bfloat16 bf16;

// ---------------- scratch (device globals; no allocations allowed) ----------
__device__ bf16  g_xn_hi[B_ * L_ * C_];
__device__ bf16  g_xn_lo[B_ * L_ * C_];
__device__ bf16  g_k_hi [B_ * L_ * D_];
__device__ bf16  g_k_lo [B_ * L_ * D_];
__device__ bf16  g_v_hi [B_ * L_ * D_];
__device__ bf16  g_v_lo [B_ * L_ * D_];
__device__ bf16  g_vT_hi[B_ * D_ * L_];
__device__ bf16  g_vT_lo[B_ * D_ * L_];
__device__ bf16  g_WqT_hi[D_ * D_],  g_WqT_lo[D_ * D_];
__device__ bf16  g_WkT_hi[D_ * C_],  g_WkT_lo[D_ * C_];
__device__ bf16  g_WvT_hi[D_ * C_],  g_WvT_lo[D_ * C_];
__device__ bf16  g_W1T_hi[MLPD * D_], g_W1T_lo[MLPD * D_];
__device__ bf16  g_W2T_hi[D_ * MLPD], g_W2T_lo[D_ * MLPD];
__device__ float g_t   [B_ * NS * D_];
__device__ bf16  g_tln_hi[B_ * NS * D_], g_tln_lo[B_ * NS * D_];
__device__ bf16  g_q_hi  [B_ * NS * D_], g_q_lo  [B_ * NS * D_];
__device__ float g_attn[B_ * L_ * NS];
__device__ bf16  g_attnT_hi[B_ * NS * L_], g_attnT_lo[B_ * NS * L_];
__device__ float g_colpart[32 * B_ * NS];
__device__ float g_colsum[B_ * NS];
__device__ bf16  g_hid_hi[B_ * NS * MLPD], g_hid_lo[B_ * NS * MLPD];
__device__ float g_upart[4 * B_ * NS * D_];   // split-K partials (33.5 MB)

// ---------------- helpers -----------------------------------------------------
__device__ __forceinline__ uint32_t smem_to_u32(const void* p) {
    uint32_t a;
    asm("{ .reg .u64 t; cvta.to.shared.u64 t, %1; cvt.u32.u64 %0, t; }"
        : "=r"(a) : "l"(p));
    return a;
}
__device__ __forceinline__ void cp16(uint32_t saddr, const void* g) {
    asm volatile("cp.async.cg.shared.global [%0], [%1], 16;" :: "r"(saddr), "l"(g));
}
#define CP_COMMIT() asm volatile("cp.async.commit_group;" ::: "memory")
#define CP_WAIT(N)  asm volatile("cp.async.wait_group %0;" :: "n"(N) : "memory")

__device__ __forceinline__ void ldm_x4(uint32_t &r0, uint32_t &r1, uint32_t &r2,
                                       uint32_t &r3, uint32_t addr) {
    asm volatile("ldmatrix.sync.aligned.m8n8.x4.shared.b16 {%0,%1,%2,%3}, [%4];"
                 : "=r"(r0), "=r"(r1), "=r"(r2), "=r"(r3) : "r"(addr));
}
__device__ __forceinline__ void mma_bf16(float* c, const uint32_t* a,
                                         uint32_t b0, uint32_t b1) {
    asm volatile("mma.sync.aligned.m16n8k16.row.col.f32.bf16.bf16.f32 "
                 "{%0,%1,%2,%3}, {%4,%5,%6,%7}, {%8,%9}, {%0,%1,%2,%3};"
                 : "+f"(c[0]), "+f"(c[1]), "+f"(c[2]), "+f"(c[3])
                 : "r"(a[0]), "r"(a[1]), "r"(a[2]), "r"(a[3]), "r"(b0), "r"(b1));
}
__device__ __forceinline__ void split_bf16(float x, bf16 &h, bf16 &l) {
    h = __float2bfloat16(x);
    l = __float2bfloat16(x - __bfloat162float(h));
}

// swizzled byte offset within one (rows x 64B) matrix buffer
__device__ __forceinline__ uint32_t swz(int row, int ch) {
    return (uint32_t)(row * 64 + ((ch ^ ((row >> 1) & 3)) << 4));
}

// ---------------- HMMA GEMM: D[M,N] = A[M,K] . B[N,K]^T (bf16 hi/lo split) ---
// Block 128 x (WN*64), BK=32, 8 warps (2m x 4n), warp tile 64 x (WN*16).
// 3-stage cp.async pipeline. Optional split-K via kslices (z encodes batch*ks).
enum { EPI_NONE = 0, EPI_SPLIT = 1, EPI_SPLIT_SCALE = 2,
       EPI_SPLIT_BIAS_RELU = 3, EPI_ADD_BIAS = 4 };

template<int EPI, int WN>
__global__ void __launch_bounds__(256)
hg_gemm(const bf16* __restrict__ AhiG, const bf16* __restrict__ AloG,
        const bf16* __restrict__ BhiG, const bf16* __restrict__ BloG,
        float* Cf32, const float* __restrict__ Cres,
        bf16* Chi, bf16* Clo, const float* __restrict__ biasg,
        float alpha, int M, int N, int K, int ldA, int ldB, int kslices,
        long batA, long batB, long batC) {
    constexpr int BN = WN * 64;
    constexpr int BSTG = 16384 + BN * 128;
    constexpr int BSH = (WN == 4) ? 10 : ((WN == 2) ? 9 : 8);

    extern __shared__ char smem[];
    const uint32_t sbase = smem_to_u32(smem);
    const int tid = threadIdx.x;
    const int wid = tid >> 5, lane = tid & 31;
    const int warp_m = wid & 1, warp_n = wid >> 1;
    const int m0 = blockIdx.y * 128;
    const int n0 = blockIdx.x * BN;
    const int z  = blockIdx.z;
    const int zb = z / kslices, ks = z - zb * kslices;

    const bf16* Ahi = AhiG + (long)zb * batA + (long)ks * K;
    const bf16* Alo = AloG + (long)zb * batA + (long)ks * K;
    const bf16* Bhi = BhiG + (long)zb * batB + (long)ks * K;
    const bf16* Blo = BloG + (long)zb * batB + (long)ks * K;
    float* Cw = Cf32 ? Cf32 + (long)z * batC : nullptr;
    const float* Cr = Cres ? Cres + (long)z * batC : nullptr;
    bf16* Ch = Chi ? Chi + (long)z * batC : nullptr;
    bf16* Cl = Clo ? Clo + (long)z * batC : nullptr;

    float acc[4][2 * WN][4];
    #pragma unroll
    for (int i = 0; i < 4; i++)
        #pragma unroll
        for (int j = 0; j < 2 * WN; j++)
            #pragma unroll
            for (int r = 0; r < 4; r++) acc[i][j][r] = 0.f;

    const int S = K / 32;

    auto load_stage = [&](int s) {
        const uint32_t sb = sbase + (uint32_t)(s % 3) * BSTG;
        const int k0 = s * 32;
        #pragma unroll
        for (int i = 0; i < 4; i++) {
            int gi = i * 256 + tid;
            int mat = gi >> 9;
            int rem = gi & 511;
            int row = rem >> 2, ch = rem & 3;
            const bf16* src = (mat ? Alo : Ahi) + (long)(m0 + row) * ldA + k0 + ch * 8;
            cp16(sb + mat * 8192 + swz(row, ch), src);
        }
        #pragma unroll
        for (int i = 0; i < BN / 32; i++) {
            int gi = i * 256 + tid;
            int mat = gi >> BSH;
            int rem = gi & ((1 << BSH) - 1);
            int row = rem >> 2, ch = rem & 3;
            const bf16* src = (mat ? Blo : Bhi) + (long)(n0 + row) * ldB + k0 + ch * 8;
            cp16(sb + 16384 + mat * (BN * 64) + swz(row, ch), src);
        }
        CP_COMMIT();
    };

    load_stage(0);
    if (S > 1) load_stage(1);

    for (int s = 0; s < S; s++) {
        if (s + 1 < S) { CP_WAIT(1); } else { CP_WAIT(0); }
        __syncthreads();
        if (s + 2 < S) load_stage(s + 2);

        const uint32_t sb = sbase + (uint32_t)(s % 3) * BSTG;
        const int lr = lane & 7, lh = (lane >> 3) & 1, lc = (lane >> 4) & 1;

        #pragma unroll
        for (int kh = 0; kh < 2; kh++) {
            uint32_t ah[4][4], al[4][4];
            #pragma unroll
            for (int tm = 0; tm < 4; tm++) {
                int row = warp_m * 64 + tm * 16 + lr + lh * 8;
                int ch  = 2 * kh + lc;
                uint32_t off = swz(row, ch);
                ldm_x4(ah[tm][0], ah[tm][1], ah[tm][2], ah[tm][3], sb + off);
                ldm_x4(al[tm][0], al[tm][1], al[tm][2], al[tm][3], sb + 8192 + off);
            }
            #pragma unroll
            for (int tnp = 0; tnp < WN; tnp++) {
                int row = warp_n * (WN * 16) + tnp * 16 + lr + lh * 8;
                int ch  = 2 * kh + lc;
                uint32_t off = swz(row, ch);
                uint32_t bh0, bh1, bh2, bh3, bl0, bl1, bl2, bl3;
                ldm_x4(bh0, bh1, bh2, bh3, sb + 16384 + off);
                ldm_x4(bl0, bl1, bl2, bl3, sb + 16384 + BN * 64 + off);
                #pragma unroll
                for (int tm = 0; tm < 4; tm++) {
                    mma_bf16(acc[tm][2*tnp],   ah[tm], bh0, bh2);
                    mma_bf16(acc[tm][2*tnp+1], ah[tm], bh1, bh3);
                    mma_bf16(acc[tm][2*tnp],   ah[tm], bl0, bl2);
                    mma_bf16(acc[tm][2*tnp+1], ah[tm], bl1, bl3);
                    mma_bf16(acc[tm][2*tnp],   al[tm], bh0, bh2);
                    mma_bf16(acc[tm][2*tnp+1], al[tm], bh1, bh3);
                }
            }
        }
    }

    #pragma unroll
    for (int tm = 0; tm < 4; tm++) {
        #pragma unroll
        for (int tn = 0; tn < 2 * WN; tn++) {
            float* c = acc[tm][tn];
            int row = m0 + warp_m * 64 + tm * 16 + (lane >> 2);
            int col = n0 + warp_n * (WN * 16) + tn * 8 + 2 * (lane & 3);
            #pragma unroll
            for (int h = 0; h < 2; h++) {
                int rw = row + h * 8;
                float v0 = c[2*h], v1 = c[2*h+1];
                long idx = (long)rw * N + col;
                if (EPI == EPI_NONE) {
                    *(float2*)(Cw + idx) = make_float2(v0, v1);
                } else if (EPI == EPI_SPLIT || EPI == EPI_SPLIT_SCALE ||
                           EPI == EPI_SPLIT_BIAS_RELU) {
                    if (EPI == EPI_SPLIT_SCALE) { v0 *= alpha; v1 *= alpha; }
                    if (EPI == EPI_SPLIT_BIAS_RELU) {
                        v0 = fmaxf(v0 + biasg[col], 0.f);
                        v1 = fmaxf(v1 + biasg[col + 1], 0.f);
                    }
                    bf16 h0, l0, h1, l1;
                    split_bf16(v0, h0, l0); split_bf16(v1, h1, l1);
                    __nv_bfloat162 ph; ph.x = h0; ph.y = h1;
                    __nv_bfloat162 pl; pl.x = l0; pl.y = l1;
                    *(__nv_bfloat162*)(Ch + idx) = ph;
                    *(__nv_bfloat162*)(Cl + idx) = pl;
                } else if (EPI == EPI_ADD_BIAS) {
                    float2 r = *(const float2*)(Cr + idx);
                    *(float2*)(Cw + idx) =
                        make_float2(r.x + v0 + biasg[col], r.y + v1 + biasg[col + 1]);
                }
            }
        }
    }
}

#define SMEM_WN4 (3 * (16384 + 256 * 128))   // 147456
#define SMEM_WN2 (3 * (16384 + 128 * 128))   // 98304
#define SMEM_WN1 (3 * (16384 + 64 * 128))    // 73728

// ---------------- fused logits GEMM + softmax + colpart + transposed split ----
// Block computes attn rows [l0, l0+128) x ALL 256 slots for batch b, then does
// softmax over N in-block, writes attn f32, column partials, attnT bf16 hi/lo.
__global__ void __launch_bounds__(256)
logits_softmax_kernel(const bf16* __restrict__ khG, const bf16* __restrict__ klG,
                      const bf16* __restrict__ qhG, const bf16* __restrict__ qlG,
                      float* __restrict__ attn,
                      bf16* __restrict__ aTh, bf16* __restrict__ aTl,
                      float* __restrict__ colpart) {
    extern __shared__ char smem[];
    const uint32_t sbase = smem_to_u32(smem);
    const int tid = threadIdx.x;
    const int wid = tid >> 5, lane = tid & 31;
    const int warp_m = wid & 1, warp_n = wid >> 1;
    const int l0 = blockIdx.x * 128;
    const int b  = blockIdx.y;

    const bf16* Ah = khG + ((long)b * L_ + l0) * D_;
    const bf16* Al = klG + ((long)b * L_ + l0) * D_;
    const bf16* Bh = qhG + (long)b * NS * D_;
    const bf16* Bl = qlG + (long)b * NS * D_;

    float acc[4][8][4];
    #pragma unroll
    for (int i = 0; i < 4; i++)
        #pragma unroll
        for (int j = 0; j < 8; j++)
            #pragma unroll
            for (int r = 0; r < 4; r++) acc[i][j][r] = 0.f;

    const int S = D_ / 32;   // 32
    auto load_stage = [&](int s) {
        const uint32_t sb = sbase + (uint32_t)(s % 3) * 49152;
        const int k0 = s * 32;
        #pragma unroll
        for (int i = 0; i < 4; i++) {
            int gi = i * 256 + tid;
            int mat = gi >> 9, rem = gi & 511, row = rem >> 2, ch = rem & 3;
            const bf16* src = (mat ? Al : Ah) + (long)row * D_ + k0 + ch * 8;
            cp16(sb + mat * 8192 + swz(row, ch), src);
        }
        #pragma unroll
        for (int i = 0; i < 8; i++) {
            int gi = i * 256 + tid;
            int mat = gi >> 10, rem = gi & 1023, row = rem >> 2, ch = rem & 3;
            const bf16* src = (mat ? Bl : Bh) + (long)row * D_ + k0 + ch * 8;
            cp16(sb + 16384 + mat * 16384 + swz(row, ch), src);
        }
        CP_COMMIT();
    };

    load_stage(0);
    load_stage(1);
    for (int s = 0; s < S; s++) {
        if (s + 1 < S) { CP_WAIT(1); } else { CP_WAIT(0); }
        __syncthreads();
        if (s + 2 < S) load_stage(s + 2);
        const uint32_t sb = sbase + (uint32_t)(s % 3) * 49152;
        const int lr = lane & 7, lh = (lane >> 3) & 1, lc = (lane >> 4) & 1;
        #pragma unroll
        for (int kh = 0; kh < 2; kh++) {
            uint32_t ah[4][4], al[4][4];
            #pragma unroll
            for (int tm = 0; tm < 4; tm++) {
                int row = warp_m * 64 + tm * 16 + lr + lh * 8;
                int ch  = 2 * kh + lc;
                uint32_t off = swz(row, ch);
                ldm_x4(ah[tm][0], ah[tm][1], ah[tm][2], ah[tm][3], sb + off);
                ldm_x4(al[tm][0], al[tm][1], al[tm][2], al[tm][3], sb + 8192 + off);
            }
            #pragma unroll
            for (int tnp = 0; tnp < 4; tnp++) {
                int row = warp_n * 64 + tnp * 16 + lr + lh * 8;
                int ch  = 2 * kh + lc;
                uint32_t off = swz(row, ch);
                uint32_t bh0, bh1, bh2, bh3, bl0, bl1, bl2, bl3;
                ldm_x4(bh0, bh1, bh2, bh3, sb + 16384 + off);
                ldm_x4(bl0, bl1, bl2, bl3, sb + 32768 + off);
                #pragma unroll
                for (int tm = 0; tm < 4; tm++) {
                    mma_bf16(acc[tm][2*tnp],   ah[tm], bh0, bh2);
                    mma_bf16(acc[tm][2*tnp+1], ah[tm], bh1, bh3);
                    mma_bf16(acc[tm][2*tnp],   ah[tm], bl0, bl2);
                    mma_bf16(acc[tm][2*tnp+1], ah[tm], bl1, bl3);
                    mma_bf16(acc[tm][2*tnp],   al[tm], bh0, bh2);
                    mma_bf16(acc[tm][2*tnp+1], al[tm], bh1, bh3);
                }
            }
        }
    }
    __syncthreads();          // everyone done reading pipeline smem

    // stage logits to smem ptile [128][257]
    float* ptile = (float*)smem;
    #pragma unroll
    for (int tm = 0; tm < 4; tm++)
        #pragma unroll
        for (int tn = 0; tn < 8; tn++) {
            int row = warp_m * 64 + tm * 16 + (lane >> 2);
            int col = warp_n * 64 + tn * 8 + 2 * (lane & 3);
            #pragma unroll
            for (int h = 0; h < 2; h++) {
                ptile[(row + h * 8) * 257 + col]     = acc[tm][tn][2*h];
                ptile[(row + h * 8) * 257 + col + 1] = acc[tm][tn][2*h+1];
            }
        }
    __syncthreads();

    // softmax over 256 cols for 16 rows per warp; accumulate column partials
    float* cpt = (float*)(smem) + 128 * 257;   // [8][256] warp col-partials
    float cacc[8];
    #pragma unroll
    for (int j = 0; j < 8; j++) cacc[j] = 0.f;
    for (int r = 0; r < 16; r++) {
        int row = wid * 16 + r;
        float v[8];
        #pragma unroll
        for (int j = 0; j < 8; j++) v[j] = ptile[row * 257 + lane + 32 * j];
        float m = v[0];
        #pragma unroll
        for (int j = 1; j < 8; j++) m = fmaxf(m, v[j]);
        #pragma unroll
        for (int o = 16; o > 0; o >>= 1) m = fmaxf(m, __shfl_xor_sync(0xffffffffu, m, o));
        float s = 0.f;
        #pragma unroll
        for (int j = 0; j < 8; j++) { v[j] = __expf(v[j] - m); s += v[j]; }
        #pragma unroll
        for (int o = 16; o > 0; o >>= 1) s += __shfl_xor_sync(0xffffffffu, s, o);
        float inv = 1.0f / s;
        float* ag = attn + ((long)b * L_ + l0 + row) * NS;
        #pragma unroll
        for (int j = 0; j < 8; j++) {
            float p = v[j] * inv + 1e-8f;
            cacc[j] += p;
            ptile[row * 257 + lane + 32 * j] = p;
            ag[lane + 32 * j] = p;
        }
    }
    #pragma unroll
    for (int j = 0; j < 8; j++) cpt[wid * 256 + lane + 32 * j] = cacc[j];
    __syncthreads();
    if (tid < 256) {
        float s = 0.f;
        #pragma unroll
        for (int w = 0; w < 8; w++) s += cpt[w * 256 + tid];
        colpart[(long)blockIdx.x * B_ * NS + b * NS + tid] = s;
    }

    // transposed hi/lo write: attnT[n, l0 + l]
    int tx = tid & 31, ty = tid >> 5;
    for (int nn = ty; nn < 256; nn += 8) {
        #pragma unroll
        for (int ls = 0; ls < 2; ls++) {
            int l = ls * 64 + tx * 2;
            float v0 = ptile[l * 257 + nn];
            float v1 = ptile[(l + 1) * 257 + nn];
            bf16 h0, o0, h1, o1;
            split_bf16(v0, h0, o0); split_bf16(v1, h1, o1);
            __nv_bfloat162 ph; ph.x = h0; ph.y = h1;
            __nv_bfloat162 pl; pl.x = o0; pl.y = o1;
            long idx = ((long)b * NS + nn) * L_ + l0 + l;
            *(__nv_bfloat162*)(aTh + idx) = ph;
            *(__nv_bfloat162*)(aTl + idx) = pl;
        }
    }
}

// ---------------- split-K reduce for the update GEMM --------------------------
__global__ void update_reduce_kernel(const float* __restrict__ part,
                                     const float* __restrict__ colsum,
                                     float* __restrict__ t) {
    int row = blockIdx.x;              // b*NS + n
    int tid = threadIdx.x;             // 256
    float inv = 1.0f / colsum[row];
    const float4* p0 = (const float4*)(part + ((long)(row * 4 + 0) & 0x7FFFFFFF, (long)0));
    // (index math below; p0 computed explicitly)
    int b = row >> 8, n = row & 255;
    const float4* q0 = (const float4*)(part + ((long)(b * 4 + 0) * NS + n) * D_);
    const float4* q1 = (const float4*)(part + ((long)(b * 4 + 1) * NS + n) * D_);
    const float4* q2 = (const float4*)(part + ((long)(b * 4 + 2) * NS + n) * D_);
    const float4* q3 = (const float4*)(part + ((long)(b * 4 + 3) * NS + n) * D_);
    float4* tp = (float4*)(t + (long)row * D_);
    float4 a = q0[tid], c = q1[tid], d = q2[tid], e = q3[tid], o = tp[tid];
    o.x += (a.x + c.x + d.x + e.x) * inv;
    o.y += (a.y + c.y + d.y + e.y) * inv;
    o.z += (a.z + c.z + d.z + e.z) * inv;
    o.w += (a.w + c.w + d.w + e.w) * inv;
    tp[tid] = o;
    (void)p0;
}

// ---------------- elementwise kernels ----------------------------------------
__global__ void bcast_templates_kernel(const float* __restrict__ tinit,
                                       float* __restrict__ t) {
    int idx = blockIdx.x * blockDim.x + threadIdx.x;
    t[idx] = tinit[idx & (NS * D_ - 1)];
}

__global__ void ln_transpose_kernel(const float* __restrict__ x,
                                    const float* __restrict__ g,
                                    const float* __restrict__ bt,
                                    bf16* __restrict__ xh, bf16* __restrict__ xl) {
    int b  = blockIdx.y;
    int l0 = blockIdx.x * 32;
    int tx = threadIdx.x, ty = threadIdx.y;           // 32 x 8
    __shared__ float ssum[8][32];
    __shared__ float ssq [8][32];
    __shared__ float smean[32], srstd[32];
    const float* xb = x + (long)b * C_ * L_;
    float s = 0.f, q = 0.f;
    for (int c = ty; c < C_; c += 8) {
        float v = xb[(long)c * L_ + l0 + tx];
        s += v; q += v * v;
    }
    ssum[ty][tx] = s; ssq[ty][tx] = q;
    __syncthreads();
    if (ty == 0) {
        float ts = 0.f, tq = 0.f;
        #pragma unroll
        for (int i = 0; i < 8; i++) { ts += ssum[i][tx]; tq += ssq[i][tx]; }
        float mean = ts * (1.0f / C_);
        float var  = tq * (1.0f / C_) - mean * mean;
        smean[tx] = mean;
        srstd[tx] = rsqrtf(var + LNEPS);
    }
    __syncthreads();
    __shared__ float tile[32][33];
    long outb = ((long)b * L_ + l0) * C_;
    for (int c0 = 0; c0 < C_; c0 += 32) {
        __syncthreads();
        for (int cc = ty; cc < 32; cc += 8) {
            float v = xb[(long)(c0 + cc) * L_ + l0 + tx];
            tile[cc][tx] = (v - smean[tx]) * srstd[tx];
        }
        __syncthreads();
        for (int ll = ty; ll < 32; ll += 8) {
            int c = c0 + tx;
            float v = tile[tx][ll] * g[c] + bt[c];
            bf16 h, l; split_bf16(v, h, l);
            long idx = outb + (long)ll * C_ + c;
            xh[idx] = h; xl[idx] = l;
        }
    }
}

__global__ void ln_rows_split_kernel(const float* __restrict__ in,
                                     const float* __restrict__ g,
                                     const float* __restrict__ bt,
                                     bf16* __restrict__ oh, bf16* __restrict__ ol) {
    int row = blockIdx.x;
    int tid = threadIdx.x;                             // 256
    const float4* pin = (const float4*)(in + (long)row * D_);
    float4 v = pin[tid];
    float s = v.x + v.y + v.z + v.w;
    float q = v.x*v.x + v.y*v.y + v.z*v.z + v.w*v.w;
    #pragma unroll
    for (int o = 16; o > 0; o >>= 1) {
        s += __shfl_down_sync(0xffffffffu, s, o);
        q += __shfl_down_sync(0xffffffffu, q, o);
    }
    __shared__ float ws[8], wq[8];
    __shared__ float smn, srs;
    int warp = tid >> 5, lane = tid & 31;
    if (lane == 0) { ws[warp] = s; wq[warp] = q; }
    __syncthreads();
    if (tid == 0) {
        float ts = 0.f, tq = 0.f;
        #pragma unroll
        for (int i = 0; i < 8; i++) { ts += ws[i]; tq += wq[i]; }
        float mean = ts * (1.0f / D_);
        float var  = tq * (1.0f / D_) - mean * mean;
        smn = mean; srs = rsqrtf(var + LNEPS);
    }
    __syncthreads();
    float mean = smn, rstd = srs;
    float4 gg = ((const float4*)g)[tid];
    float4 bb = ((const float4*)bt)[tid];
    float o0 = (v.x - mean) * rstd * gg.x + bb.x;
    float o1 = (v.y - mean) * rstd * gg.y + bb.y;
    float o2 = (v.z - mean) * rstd * gg.z + bb.z;
    float o3 = (v.w - mean) * rstd * gg.w + bb.w;
    bf16 h0,l0,h1,l1,h2,l2,h3,l3;
    split_bf16(o0,h0,l0); split_bf16(o1,h1,l1);
    split_bf16(o2,h2,l2); split_bf16(o3,h3,l3);
    __nv_bfloat162* ph = (__nv_bfloat162*)(oh + (long)row * D_);
    __nv_bfloat162* pl = (__nv_bfloat162*)(ol + (long)row * D_);
    __nv_bfloat162 a; a.x=h0; a.y=h1; ph[tid*2]=a; a.x=h2; a.y=h3; ph[tid*2+1]=a;
    __nv_bfloat162 c; c.x=l0; c.y=l1; pl[tid*2]=c; c.x=l2; c.y=l3; pl[tid*2+1]=c;
}

__global__ void colreduce_kernel(const float* __restrict__ part,
                                 float* __restrict__ colsum) {
    int idx = blockIdx.x * blockDim.x + threadIdx.x;
    float s = 0.f;
    #pragma unroll
    for (int c = 0; c < 32; c++) s += part[(long)c * B_ * NS + idx];
    colsum[idx] = s;
}

// transpose + split: in f32 [R, Ccols] -> out hi/lo bf16 [Ccols, R]  (batched)
__global__ void transpose_split_kernel(const float* __restrict__ inG,
                                       bf16* __restrict__ ohG, bf16* __restrict__ olG,
                                       int R, int Ccols, long batIn, long batOut) {
    const float* in = inG + (long)blockIdx.z * batIn;
    bf16* oh = ohG + (long)blockIdx.z * batOut;
    bf16* ol = olG + (long)blockIdx.z * batOut;
    int r0 = blockIdx.x * 32, c0 = blockIdx.y * 32;
    __shared__ float tile[32][33];
    int tx = threadIdx.x, ty = threadIdx.y;            // 32 x 8
    for (int rr = ty; rr < 32; rr += 8)
        tile[rr][tx] = in[(long)(r0 + rr) * Ccols + c0 + tx];
    __syncthreads();
    for (int cc = ty; cc < 32; cc += 8) {
        float v = tile[tx][cc];
        bf16 h, l; split_bf16(v, h, l);
        long idx = (long)(c0 + cc) * R + r0 + tx;
        oh[idx] = h; ol[idx] = l;
    }
}

__global__ void transpose_bf16_kernel(const bf16* __restrict__ ihG, const bf16* __restrict__ ilG,
                                      bf16* __restrict__ ohG, bf16* __restrict__ olG,
                                      int R, int Ccols, long batIn, long batOut) {
    const bf16* ih = ihG + (long)blockIdx.z * batIn;
    const bf16* il = ilG + (long)blockIdx.z * batIn;
    bf16* oh = ohG + (long)blockIdx.z * batOut;
    bf16* ol = olG + (long)blockIdx.z * batOut;
    int r0 = blockIdx.x * 32, c0 = blockIdx.y * 32;
    __shared__ bf16 th[32][33];
    __shared__ bf16 tl[32][33];
    int tx = threadIdx.x, ty = threadIdx.y;            // 32 x 8
    for (int rr = ty; rr < 32; rr += 8) {
        long idx = (long)(r0 + rr) * Ccols + c0 + tx;
        th[rr][tx] = ih[idx]; tl[rr][tx] = il[idx];
    }
    __syncthreads();
    for (int cc = ty; cc < 32; cc += 8) {
        long idx = (long)(c0 + cc) * R + r0 + tx;
        oh[idx] = th[tx][cc]; ol[idx] = tl[tx][cc];
    }
}

// ---------------- outputs ----------------------------------------------------
__global__ void out_templates_kernel(const float* __restrict__ t, float* __restrict__ out) {
    int b  = blockIdx.z;
    int d0 = blockIdx.x * 32, n0 = blockIdx.y * 32;
    __shared__ float tile[32][33];
    int tx = threadIdx.x, ty = threadIdx.y;
    const float* tb = t + ((long)b * NS + n0) * D_ + d0;
    for (int nn = ty; nn < 32; nn += 8)
        tile[nn][tx] = tb[(long)nn * D_ + tx];
    __syncthreads();
    float* ob = out + ((long)b * D_ + d0) * NS + n0;
    for (int dd = ty; dd < 32; dd += 8)
        ob[(long)dd * NS + tx] = tile[tx][dd];
}

__global__ void out_attn_kernel(const float* __restrict__ attn,
                                const float* __restrict__ colsum,
                                float* __restrict__ out) {
    int b  = blockIdx.z;
    int l0 = blockIdx.x * 32, n0 = blockIdx.y * 32;
    __shared__ float tile[32][33];
    __shared__ float sinv[32];
    int tx = threadIdx.x, ty = threadIdx.y;
    if (ty == 0) sinv[tx] = 1.0f / colsum[b * NS + n0 + tx];
    __syncthreads();
    const float* ab = attn + ((long)b * L_ + l0) * NS + n0;
    for (int ll = ty; ll < 32; ll += 8)
        tile[ll][tx] = ab[(long)ll * NS + tx] * sinv[tx];
    __syncthreads();
    float* ob = out + ((long)b * NS + n0) * L_ + l0;
    for (int nn = ty; nn < 32; nn += 8)
        ob[(long)nn * L_ + tx] = tile[tx][nn];
}

// ---------------- driver -----------------------------------------------------
extern "C" void kernel_launch(void* const* d_in, const int* in_sizes, int n_in,
                              void* d_out, int out_size) {
    const float* x       = (const float*)d_in[0];
    const float* tinit   = (const float*)d_in[1];
    const float* Wq      = (const float*)d_in[2];
    const float* Wk      = (const float*)d_in[3];
    const float* Wv      = (const float*)d_in[4];
    const float* ln_in_g = (const float*)d_in[5];
    const float* ln_in_b = (const float*)d_in[6];
    const float* ln_t_g  = (const float*)d_in[7];
    const float* ln_t_b  = (const float*)d_in[8];
    const float* ln_m_g  = (const float*)d_in[9];
    const float* ln_m_b  = (const float*)d_in[10];
    const float* W1      = (const float*)d_in[11];
    const float* b1      = (const float*)d_in[12];
    const float* W2      = (const float*)d_in[13];
    const float* b2      = (const float*)d_in[14];
    float* out = (float*)d_out;

    cudaFuncSetAttribute(hg_gemm<EPI_SPLIT, 4>,          cudaFuncAttributeMaxDynamicSharedMemorySize, SMEM_WN4);
    cudaFuncSetAttribute(hg_gemm<EPI_SPLIT_SCALE, 1>,    cudaFuncAttributeMaxDynamicSharedMemorySize, SMEM_WN1);
    cudaFuncSetAttribute(hg_gemm<EPI_NONE, 2>,           cudaFuncAttributeMaxDynamicSharedMemorySize, SMEM_WN2);
    cudaFuncSetAttribute(hg_gemm<EPI_SPLIT_BIAS_RELU, 2>,cudaFuncAttributeMaxDynamicSharedMemorySize, SMEM_WN2);
    cudaFuncSetAttribute(hg_gemm<EPI_ADD_BIAS, 2>,       cudaFuncAttributeMaxDynamicSharedMemorySize, SMEM_WN2);
    cudaFuncSetAttribute(logits_softmax_kernel,          cudaFuncAttributeMaxDynamicSharedMemorySize, SMEM_WN4);

    bf16 *xnh, *xnl, *kh, *kl, *vh, *vl, *vTh, *vTl;
    bf16 *WqTh, *WqTl, *WkTh, *WkTl, *WvTh, *WvTl, *W1Th, *W1Tl, *W2Th, *W2Tl;
    bf16 *tlnh, *tlnl, *qh, *ql, *aTh, *aTl, *hidh, *hidl;
    float *t, *attn, *colpart, *colsum, *upart;
    cudaGetSymbolAddress((void**)&xnh, g_xn_hi);   cudaGetSymbolAddress((void**)&xnl, g_xn_lo);
    cudaGetSymbolAddress((void**)&kh,  g_k_hi);    cudaGetSymbolAddress((void**)&kl,  g_k_lo);
    cudaGetSymbolAddress((void**)&vh,  g_v_hi);    cudaGetSymbolAddress((void**)&vl,  g_v_lo);
    cudaGetSymbolAddress((void**)&vTh, g_vT_hi);   cudaGetSymbolAddress((void**)&vTl, g_vT_lo);
    cudaGetSymbolAddress((void**)&WqTh, g_WqT_hi); cudaGetSymbolAddress((void**)&WqTl, g_WqT_lo);
    cudaGetSymbolAddress((void**)&WkTh, g_WkT_hi); cudaGetSymbolAddress((void**)&WkTl, g_WkT_lo);
    cudaGetSymbolAddress((void**)&WvTh, g_WvT_hi); cudaGetSymbolAddress((void**)&WvTl, g_WvT_lo);
    cudaGetSymbolAddress((void**)&W1Th, g_W1T_hi); cudaGetSymbolAddress((void**)&W1Tl, g_W1T_lo);
    cudaGetSymbolAddress((void**)&W2Th, g_W2T_hi); cudaGetSymbolAddress((void**)&W2Tl, g_W2T_lo);
    cudaGetSymbolAddress((void**)&tlnh, g_tln_hi); cudaGetSymbolAddress((void**)&tlnl, g_tln_lo);
    cudaGetSymbolAddress((void**)&qh,  g_q_hi);    cudaGetSymbolAddress((void**)&ql,  g_q_lo);
    cudaGetSymbolAddress((void**)&aTh, g_attnT_hi);cudaGetSymbolAddress((void**)&aTl, g_attnT_lo);
    cudaGetSymbolAddress((void**)&hidh, g_hid_hi); cudaGetSymbolAddress((void**)&hidl, g_hid_lo);
    cudaGetSymbolAddress((void**)&t,    g_t);
    cudaGetSymbolAddress((void**)&attn, g_attn);
    cudaGetSymbolAddress((void**)&colpart, g_colpart);
    cudaGetSymbolAddress((void**)&colsum,  g_colsum);
    cudaGetSymbolAddress((void**)&upart,   g_upart);

    const float scale = 0.03125f;  // 1024^-0.5
    dim3 tb32(32, 8);

    bcast_templates_kernel<<<8192, 256>>>(tinit, t);
    ln_transpose_kernel<<<dim3(L_ / 32, B_), tb32>>>(x, ln_in_g, ln_in_b, xnh, xnl);

    transpose_split_kernel<<<dim3(C_/32, D_/32, 1), tb32>>>(Wq, WqTh, WqTl, C_, D_, 0, 0);
    transpose_split_kernel<<<dim3(C_/32, D_/32, 1), tb32>>>(Wk, WkTh, WkTl, C_, D_, 0, 0);
    transpose_split_kernel<<<dim3(C_/32, D_/32, 1), tb32>>>(Wv, WvTh, WvTl, C_, D_, 0, 0);
    transpose_split_kernel<<<dim3(D_/32, MLPD/32, 1), tb32>>>(W1, W1Th, W1Tl, D_, MLPD, 0, 0);
    transpose_split_kernel<<<dim3(MLPD/32, D_/32, 1), tb32>>>(W2, W2Th, W2Tl, MLPD, D_, 0, 0);

    // k = xn @ Wk ; v = xn @ Wv  -> bf16 hi/lo   (128x256 tiles)
    hg_gemm<EPI_SPLIT, 4><<<dim3(D_/256, (B_*L_)/128, 1), 256, SMEM_WN4>>>(
        xnh, xnl, WkTh, WkTl, nullptr, nullptr, kh, kl, nullptr,
        1.f, B_*L_, D_, C_, C_, C_, 1, 0, 0, 0);
    hg_gemm<EPI_SPLIT, 4><<<dim3(D_/256, (B_*L_)/128, 1), 256, SMEM_WN4>>>(
        xnh, xnl, WvTh, WvTl, nullptr, nullptr, vh, vl, nullptr,
        1.f, B_*L_, D_, C_, C_, C_, 1, 0, 0, 0);
    transpose_bf16_kernel<<<dim3(L_/32, D_/32, B_), tb32>>>(
        vh, vl, vTh, vTl, L_, D_, (long)L_*D_, (long)D_*L_);

    for (int it = 0; it < TIT; it++) {
        ln_rows_split_kernel<<<B_*NS, 256>>>(t, ln_t_g, ln_t_b, tlnh, tlnl);
        // q = LN(t) @ Wq * scale  (64-wide tiles: 256 CTAs)
        hg_gemm<EPI_SPLIT_SCALE, 1><<<dim3(D_/64, (B_*NS)/128, 1), 256, SMEM_WN1>>>(
            tlnh, tlnl, WqTh, WqTl, nullptr, nullptr, qh, ql, nullptr,
            scale, B_*NS, D_, D_, D_, D_, 1, 0, 0, 0);
        // fused: logits + softmax + col partials + transposed hi/lo split
        logits_softmax_kernel<<<dim3(L_/128, B_), 256, SMEM_WN4>>>(
            kh, kl, qh, ql, attn, aTh, aTl, colpart);
        colreduce_kernel<<<8, 256>>>(colpart, colsum);
        // update partials: split-K x4 over L, one launch, 512 CTAs
        hg_gemm<EPI_NONE, 2><<<dim3(D_/128, NS/128, B_*4), 256, SMEM_WN2>>>(
            aTh, aTl, vTh, vTl, upart, nullptr, nullptr, nullptr, nullptr,
            1.f, NS, D_, L_/4, L_, L_, 4, (long)NS*L_, (long)D_*L_, (long)NS*D_);
        update_reduce_kernel<<<B_*NS, 256>>>(upart, colsum, t);
        // MLP residual
        ln_rows_split_kernel<<<B_*NS, 256>>>(t, ln_m_g, ln_m_b, tlnh, tlnl);
        hg_gemm<EPI_SPLIT_BIAS_RELU, 2><<<dim3(MLPD/128, (B_*NS)/128, 1), 256, SMEM_WN2>>>(
            tlnh, tlnl, W1Th, W1Tl, nullptr, nullptr, hidh, hidl, b1,
            1.f, B_*NS, MLPD, D_, D_, D_, 1, 0, 0, 0);
        hg_gemm<EPI_ADD_BIAS, 2><<<dim3(D_/128, (B_*NS)/128, 1), 256, SMEM_WN2>>>(
            hidh, hidl, W2Th, W2Tl, t, t, nullptr, nullptr, b2,
            1.f, B_*NS, D_, MLPD, MLPD, MLPD, 1, 0, 0, (long)NS*D_*0 + 0);
    }

    out_templates_kernel<<<dim3(D_/32, NS/32, B_), tb32>>>(t, out);
    out_attn_kernel<<<dim3(L_/32, NS/32, B_), tb32>>>(
        attn, colsum, out + (long)B_ * D_ * NS);
}

// round 14
// speedup vs baseline: 1.5208x; 1.5208x over previous
#include <cuda_runtime.h>
#include <cuda_bf16.h>
#include <cstdint>

#define B_   8
#define L_   4096
#define C_   1024
#define D_   1024
#define NS   256
#define MLPD 512
#define TIT  6
#define LNEPS 1e-5f

typedef unsigned long long u64;
typedef __nv_bfloat16 bf16;

// ---------------- scratch (device globals; no allocations allowed) ----------
__device__ bf16  g_xn_hi[B_ * L_ * C_];
__device__ bf16  g_xn_lo[B_ * L_ * C_];
__device__ bf16  g_k_hi [B_ * L_ * D_];
__device__ bf16  g_k_lo [B_ * L_ * D_];
__device__ bf16  g_v_hi [B_ * L_ * D_];
__device__ bf16  g_v_lo [B_ * L_ * D_];
__device__ bf16  g_vT_hi[B_ * D_ * L_];
__device__ bf16  g_vT_lo[B_ * D_ * L_];
__device__ bf16  g_WqT_hi[D_ * D_],  g_WqT_lo[D_ * D_];
__device__ bf16  g_WkT_hi[D_ * C_],  g_WkT_lo[D_ * C_];
__device__ bf16  g_WvT_hi[D_ * C_],  g_WvT_lo[D_ * C_];
__device__ bf16  g_W1T_hi[MLPD * D_], g_W1T_lo[MLPD * D_];
__device__ bf16  g_W2T_hi[D_ * MLPD], g_W2T_lo[D_ * MLPD];
__device__ float g_t   [B_ * NS * D_];
__device__ bf16  g_tln_hi[B_ * NS * D_], g_tln_lo[B_ * NS * D_];
__device__ bf16  g_q_hi  [B_ * NS * D_], g_q_lo  [B_ * NS * D_];
__device__ float g_attn[B_ * L_ * NS];
__device__ bf16  g_attnT_hi[B_ * NS * L_], g_attnT_lo[B_ * NS * L_];
__device__ float g_colpart[32 * B_ * NS];
__device__ float g_colsum[B_ * NS];
__device__ bf16  g_hid_hi[B_ * NS * MLPD], g_hid_lo[B_ * NS * MLPD];

// ---------------- helpers -----------------------------------------------------
__device__ __forceinline__ uint32_t smem_to_u32(const void* p) {
    uint32_t a;
    asm("{ .reg .u64 t; cvta.to.shared.u64 t, %1; cvt.u32.u64 %0, t; }"
        : "=r"(a) : "l"(p));
    return a;
}
__device__ __forceinline__ void cp16(uint32_t saddr, const void* g) {
    asm volatile("cp.async.cg.shared.global [%0], [%1], 16;" :: "r"(saddr), "l"(g));
}
#define CP_COMMIT() asm volatile("cp.async.commit_group;" ::: "memory")
#define CP_WAIT(N)  asm volatile("cp.async.wait_group %0;" :: "n"(N) : "memory")

__device__ __forceinline__ void ldm_x4(uint32_t &r0, uint32_t &r1, uint32_t &r2,
                                       uint32_t &r3, uint32_t addr) {
    asm volatile("ldmatrix.sync.aligned.m8n8.x4.shared.b16 {%0,%1,%2,%3}, [%4];"
                 : "=r"(r0), "=r"(r1), "=r"(r2), "=r"(r3) : "r"(addr));
}
__device__ __forceinline__ void mma_bf16(float* c, const uint32_t* a,
                                         uint32_t b0, uint32_t b1) {
    asm volatile("mma.sync.aligned.m16n8k16.row.col.f32.bf16.bf16.f32 "
                 "{%0,%1,%2,%3}, {%4,%5,%6,%7}, {%8,%9}, {%0,%1,%2,%3};"
                 : "+f"(c[0]), "+f"(c[1]), "+f"(c[2]), "+f"(c[3])
                 : "r"(a[0]), "r"(a[1]), "r"(a[2]), "r"(a[3]), "r"(b0), "r"(b1));
}
__device__ __forceinline__ void split_bf16(float x, bf16 &h, bf16 &l) {
    h = __float2bfloat16(x);
    l = __float2bfloat16(x - __bfloat162float(h));
}

// ---------------- HMMA GEMM: D[M,N] = A[M,K] . B[N,K]^T (bf16 hi/lo split) ---
// Block 128x128, BK=32, 8 warps (2m x 4n), warp tile 64x32, m16n8k16 frags.
// smem per stage: Ah(8K) Al(8K) Bh(8K) Bl(8K) = 32KB; double buffered = 64KB.
// __launch_bounds__(256, 2): cap regs at 128 -> 2 CTAs/SM (16 warps).
enum { EPI_NONE = 0, EPI_SPLIT = 1, EPI_SPLIT_SCALE = 2,
       EPI_SPLIT_BIAS_RELU = 3, EPI_ADD_BIAS = 4, EPI_UPDATE = 5 };

#define HG_SMEM 65536
#define STG 32768

// swizzled byte offset within one 128x(4x16B) matrix buffer
__device__ __forceinline__ uint32_t swz(int row, int ch) {
    return (uint32_t)(row * 64 + ((ch ^ ((row >> 1) & 3)) << 4));
}

template<int EPI>
__global__ void __launch_bounds__(256, 2)
hg_gemm(const bf16* __restrict__ AhiG, const bf16* __restrict__ AloG,
        const bf16* __restrict__ BhiG, const bf16* __restrict__ BloG,
        float* Cf32, const float* __restrict__ Cres,
        bf16* Chi, bf16* Clo,
        const float* __restrict__ biasg, const float* __restrict__ rsg,
        float alpha, int M, int N, int K,
        long batA, long batB, long batC, int batS) {
    extern __shared__ char smem[];
    const uint32_t sbase = smem_to_u32(smem);
    const int tid = threadIdx.x;
    const int wid = tid >> 5, lane = tid & 31;
    const int warp_m = wid & 1, warp_n = wid >> 1;
    const int m0 = blockIdx.y * 128;
    const int n0 = blockIdx.x * 128;
    const int z  = blockIdx.z;

    const bf16* Ahi = AhiG + (long)z * batA;
    const bf16* Alo = AloG + (long)z * batA;
    const bf16* Bhi = BhiG + (long)z * batB;
    const bf16* Blo = BloG + (long)z * batB;
    float* Cw = Cf32 ? Cf32 + (long)z * batC : nullptr;
    const float* Cr = Cres ? Cres + (long)z * batC : nullptr;
    bf16* Ch = Chi ? Chi + (long)z * batC : nullptr;
    bf16* Cl = Clo ? Clo + (long)z * batC : nullptr;
    const float* RS = rsg ? rsg + (long)z * batS : nullptr;

    float acc[4][4][4];
    #pragma unroll
    for (int i = 0; i < 4; i++)
        #pragma unroll
        for (int j = 0; j < 4; j++)
            #pragma unroll
            for (int r = 0; r < 4; r++) acc[i][j][r] = 0.f;

    const int S = K / 32;

    // stage loader: 4 matrices x 128 rows x 4 chunks(16B) = 2048 cp.async
    auto load_stage = [&](int s) {
        const int p = s & 1;
        const int k0 = s * 32;
        const uint32_t sb = sbase + p * STG;
        #pragma unroll
        for (int i = 0; i < 8; i++) {
            int gi = i * 256 + tid;
            int mat = gi >> 9;
            int rem = gi & 511;
            int row = rem >> 2;
            int ch  = rem & 3;
            const bf16* src;
            if (mat == 0)      src = Ahi + (long)(m0 + row) * K + k0 + ch * 8;
            else if (mat == 1) src = Alo + (long)(m0 + row) * K + k0 + ch * 8;
            else if (mat == 2) src = Bhi + (long)(n0 + row) * K + k0 + ch * 8;
            else               src = Blo + (long)(n0 + row) * K + k0 + ch * 8;
            cp16(sb + mat * 8192 + swz(row, ch), src);
        }
        CP_COMMIT();
    };

    load_stage(0);

    for (int s = 0; s < S; s++) {
        const bool more = (s + 1 < S);
        if (more) load_stage(s + 1);
        if (more) { CP_WAIT(1); } else { CP_WAIT(0); }
        __syncthreads();

        const uint32_t sb = sbase + (s & 1) * STG;
        const int lr = lane & 7, lh = (lane >> 3) & 1, lc = (lane >> 4) & 1;

        #pragma unroll
        for (int kh = 0; kh < 2; kh++) {
            uint32_t ah[4][4], al[4][4];
            #pragma unroll
            for (int tm = 0; tm < 4; tm++) {
                int row = warp_m * 64 + tm * 16 + lr + lh * 8;
                int ch  = 2 * kh + lc;
                uint32_t off = swz(row, ch);
                ldm_x4(ah[tm][0], ah[tm][1], ah[tm][2], ah[tm][3], sb + off);
                ldm_x4(al[tm][0], al[tm][1], al[tm][2], al[tm][3], sb + 8192 + off);
            }
            #pragma unroll
            for (int tnp = 0; tnp < 2; tnp++) {
                int row = warp_n * 32 + tnp * 16 + lr + lh * 8;
                int ch  = 2 * kh + lc;
                uint32_t off = swz(row, ch);
                uint32_t bh0, bh1, bh2, bh3, bl0, bl1, bl2, bl3;
                ldm_x4(bh0, bh1, bh2, bh3, sb + 16384 + off);
                ldm_x4(bl0, bl1, bl2, bl3, sb + 24576 + off);
                #pragma unroll
                for (int tm = 0; tm < 4; tm++) {
                    mma_bf16(acc[tm][2*tnp],   ah[tm], bh0, bh2);
                    mma_bf16(acc[tm][2*tnp+1], ah[tm], bh1, bh3);
                    mma_bf16(acc[tm][2*tnp],   ah[tm], bl0, bl2);
                    mma_bf16(acc[tm][2*tnp+1], ah[tm], bl1, bl3);
                    mma_bf16(acc[tm][2*tnp],   al[tm], bh0, bh2);
                    mma_bf16(acc[tm][2*tnp+1], al[tm], bh1, bh3);
                }
            }
        }
        __syncthreads();
    }

    // epilogue: thread t of warp holds (m = tile_m*16 + lane/4 (+8), n = tile_n*8 + 2*(lane%4) (+1))
    #pragma unroll
    for (int tm = 0; tm < 4; tm++) {
        #pragma unroll
        for (int tn = 0; tn < 4; tn++) {
            float* c = acc[tm][tn];
            int row = m0 + warp_m * 64 + tm * 16 + (lane >> 2);
            int col = n0 + warp_n * 32 + tn * 8 + 2 * (lane & 3);
            #pragma unroll
            for (int h = 0; h < 2; h++) {
                int rw = row + h * 8;
                float v0 = c[2*h], v1 = c[2*h+1];
                long idx = (long)rw * N + col;
                if (EPI == EPI_NONE) {
                    *(float2*)(Cw + idx) = make_float2(v0, v1);
                } else if (EPI == EPI_SPLIT || EPI == EPI_SPLIT_SCALE ||
                           EPI == EPI_SPLIT_BIAS_RELU) {
                    if (EPI == EPI_SPLIT_SCALE) { v0 *= alpha; v1 *= alpha; }
                    if (EPI == EPI_SPLIT_BIAS_RELU) {
                        v0 = fmaxf(v0 + biasg[col], 0.f);
                        v1 = fmaxf(v1 + biasg[col + 1], 0.f);
                    }
                    bf16 h0, l0, h1, l1;
                    split_bf16(v0, h0, l0); split_bf16(v1, h1, l1);
                    __nv_bfloat162 ph; ph.x = h0; ph.y = h1;
                    __nv_bfloat162 pl; pl.x = l0; pl.y = l1;
                    *(__nv_bfloat162*)(Ch + idx) = ph;
                    *(__nv_bfloat162*)(Cl + idx) = pl;
                } else if (EPI == EPI_ADD_BIAS) {
                    float2 r = *(const float2*)(Cr + idx);
                    *(float2*)(Cw + idx) =
                        make_float2(r.x + v0 + biasg[col], r.y + v1 + biasg[col + 1]);
                } else if (EPI == EPI_UPDATE) {
                    float rs = 1.0f / RS[rw];
                    float2 r = *(const float2*)(Cr + idx);
                    *(float2*)(Cw + idx) = make_float2(r.x + v0 * rs, r.y + v1 * rs);
                }
            }
        }
    }
}

// ---------------- elementwise kernels ----------------------------------------
__global__ void bcast_templates_kernel(const float* __restrict__ tinit,
                                       float* __restrict__ t) {
    int idx = blockIdx.x * blockDim.x + threadIdx.x;
    t[idx] = tinit[idx & (NS * D_ - 1)];
}

// LN over channels + transpose: x[B,C,L] -> xn hi/lo [B,L,C]
__global__ void ln_transpose_kernel(const float* __restrict__ x,
                                    const float* __restrict__ g,
                                    const float* __restrict__ bt,
                                    bf16* __restrict__ xh, bf16* __restrict__ xl) {
    int b  = blockIdx.y;
    int l0 = blockIdx.x * 32;
    int tx = threadIdx.x, ty = threadIdx.y;           // 32 x 8
    __shared__ float ssum[8][32];
    __shared__ float ssq [8][32];
    __shared__ float smean[32], srstd[32];
    const float* xb = x + (long)b * C_ * L_;
    float s = 0.f, q = 0.f;
    for (int c = ty; c < C_; c += 8) {
        float v = xb[(long)c * L_ + l0 + tx];
        s += v; q += v * v;
    }
    ssum[ty][tx] = s; ssq[ty][tx] = q;
    __syncthreads();
    if (ty == 0) {
        float ts = 0.f, tq = 0.f;
        #pragma unroll
        for (int i = 0; i < 8; i++) { ts += ssum[i][tx]; tq += ssq[i][tx]; }
        float mean = ts * (1.0f / C_);
        float var  = tq * (1.0f / C_) - mean * mean;
        smean[tx] = mean;
        srstd[tx] = rsqrtf(var + LNEPS);
    }
    __syncthreads();
    __shared__ float tile[32][33];
    long outb = ((long)b * L_ + l0) * C_;
    for (int c0 = 0; c0 < C_; c0 += 32) {
        __syncthreads();
        for (int cc = ty; cc < 32; cc += 8) {
            float v = xb[(long)(c0 + cc) * L_ + l0 + tx];
            tile[cc][tx] = (v - smean[tx]) * srstd[tx];
        }
        __syncthreads();
        for (int ll = ty; ll < 32; ll += 8) {
            int c = c0 + tx;
            float v = tile[tx][ll] * g[c] + bt[c];
            bf16 h, l; split_bf16(v, h, l);
            long idx = outb + (long)ll * C_ + c;
            xh[idx] = h; xl[idx] = l;
        }
    }
}

// LN over rows of [rows, 1024], split output
__global__ void ln_rows_split_kernel(const float* __restrict__ in,
                                     const float* __restrict__ g,
                                     const float* __restrict__ bt,
                                     bf16* __restrict__ oh, bf16* __restrict__ ol) {
    int row = blockIdx.x;
    int tid = threadIdx.x;                             // 256
    const float4* pin = (const float4*)(in + (long)row * D_);
    float4 v = pin[tid];
    float s = v.x + v.y + v.z + v.w;
    float q = v.x*v.x + v.y*v.y + v.z*v.z + v.w*v.w;
    #pragma unroll
    for (int o = 16; o > 0; o >>= 1) {
        s += __shfl_down_sync(0xffffffffu, s, o);
        q += __shfl_down_sync(0xffffffffu, q, o);
    }
    __shared__ float ws[8], wq[8];
    __shared__ float smn, srs;
    int warp = tid >> 5, lane = tid & 31;
    if (lane == 0) { ws[warp] = s; wq[warp] = q; }
    __syncthreads();
    if (tid == 0) {
        float ts = 0.f, tq = 0.f;
        #pragma unroll
        for (int i = 0; i < 8; i++) { ts += ws[i]; tq += wq[i]; }
        float mean = ts * (1.0f / D_);
        float var  = tq * (1.0f / D_) - mean * mean;
        smn = mean; srs = rsqrtf(var + LNEPS);
    }
    __syncthreads();
    float mean = smn, rstd = srs;
    float4 gg = ((const float4*)g)[tid];
    float4 bb = ((const float4*)bt)[tid];
    float o0 = (v.x - mean) * rstd * gg.x + bb.x;
    float o1 = (v.y - mean) * rstd * gg.y + bb.y;
    float o2 = (v.z - mean) * rstd * gg.z + bb.z;
    float o3 = (v.w - mean) * rstd * gg.w + bb.w;
    bf16 h0,l0,h1,l1,h2,l2,h3,l3;
    split_bf16(o0,h0,l0); split_bf16(o1,h1,l1);
    split_bf16(o2,h2,l2); split_bf16(o3,h3,l3);
    __nv_bfloat162* ph = (__nv_bfloat162*)(oh + (long)row * D_);
    __nv_bfloat162* pl = (__nv_bfloat162*)(ol + (long)row * D_);
    __nv_bfloat162 a; a.x=h0; a.y=h1; ph[tid*2]=a; a.x=h2; a.y=h3; ph[tid*2+1]=a;
    __nv_bfloat162 c; c.x=l0; c.y=l1; pl[tid*2]=c; c.x=l2; c.y=l3; pl[tid*2+1]=c;
}

// softmax over N (row of 256), one warp per row
__global__ void softmax_kernel(float* __restrict__ attn) {
    int warp = threadIdx.x >> 5, lane = threadIdx.x & 31;
    long row = (long)blockIdx.x * 8 + warp;
    float* p = attn + row * NS;
    float4 a = ((float4*)p)[lane];
    float4 c = ((float4*)p)[lane + 32];
    float m = fmaxf(fmaxf(fmaxf(a.x, a.y), fmaxf(a.z, a.w)),
                    fmaxf(fmaxf(c.x, c.y), fmaxf(c.z, c.w)));
    #pragma unroll
    for (int o = 16; o > 0; o >>= 1) m = fmaxf(m, __shfl_xor_sync(0xffffffffu, m, o));
    a.x = __expf(a.x - m); a.y = __expf(a.y - m);
    a.z = __expf(a.z - m); a.w = __expf(a.w - m);
    c.x = __expf(c.x - m); c.y = __expf(c.y - m);
    c.z = __expf(c.z - m); c.w = __expf(c.w - m);
    float s = (a.x + a.y + a.z + a.w) + (c.x + c.y + c.z + c.w);
    #pragma unroll
    for (int o = 16; o > 0; o >>= 1) s += __shfl_xor_sync(0xffffffffu, s, o);
    float inv = 1.0f / s;
    a.x = a.x * inv + 1e-8f; a.y = a.y * inv + 1e-8f;
    a.z = a.z * inv + 1e-8f; a.w = a.w * inv + 1e-8f;
    c.x = c.x * inv + 1e-8f; c.y = c.y * inv + 1e-8f;
    c.z = c.z * inv + 1e-8f; c.w = c.w * inv + 1e-8f;
    ((float4*)p)[lane]      = a;
    ((float4*)p)[lane + 32] = c;
}

// deterministic column sums over L
__global__ void colpart_kernel(const float* __restrict__ attn,
                               float* __restrict__ part) {
    int b  = blockIdx.y;
    int ch = blockIdx.x;
    int n  = threadIdx.x;
    const float* p = attn + ((long)b * L_ + ch * 128) * NS + n;
    float s0 = 0.f, s1 = 0.f, s2 = 0.f, s3 = 0.f;
    #pragma unroll 4
    for (int i = 0; i < 128; i += 4) {
        s0 += p[(long)(i+0) * NS]; s1 += p[(long)(i+1) * NS];
        s2 += p[(long)(i+2) * NS]; s3 += p[(long)(i+3) * NS];
    }
    part[(long)ch * B_ * NS + b * NS + n] = (s0 + s1) + (s2 + s3);
}
__global__ void colreduce_kernel(const float* __restrict__ part,
                                 float* __restrict__ colsum) {
    int idx = blockIdx.x * blockDim.x + threadIdx.x;
    float s = 0.f;
    #pragma unroll
    for (int c = 0; c < 32; c++) s += part[(long)c * B_ * NS + idx];
    colsum[idx] = s;
}

// transpose + split: in f32 [R, Ccols] -> out hi/lo bf16 [Ccols, R]  (batched)
__global__ void transpose_split_kernel(const float* __restrict__ inG,
                                       bf16* __restrict__ ohG, bf16* __restrict__ olG,
                                       int R, int Ccols, long batIn, long batOut) {
    const float* in = inG + (long)blockIdx.z * batIn;
    bf16* oh = ohG + (long)blockIdx.z * batOut;
    bf16* ol = olG + (long)blockIdx.z * batOut;
    int r0 = blockIdx.x * 32, c0 = blockIdx.y * 32;
    __shared__ float tile[32][33];
    int tx = threadIdx.x, ty = threadIdx.y;            // 32 x 8
    for (int rr = ty; rr < 32; rr += 8)
        tile[rr][tx] = in[(long)(r0 + rr) * Ccols + c0 + tx];
    __syncthreads();
    for (int cc = ty; cc < 32; cc += 8) {
        float v = tile[tx][cc];
        bf16 h, l; split_bf16(v, h, l);
        long idx = (long)(c0 + cc) * R + r0 + tx;
        oh[idx] = h; ol[idx] = l;
    }
}

// transpose bf16 pair: in hi/lo [R, Ccols] -> out hi/lo [Ccols, R]  (batched)
__global__ void transpose_bf16_kernel(const bf16* __restrict__ ihG, const bf16* __restrict__ ilG,
                                      bf16* __restrict__ ohG, bf16* __restrict__ olG,
                                      int R, int Ccols, long batIn, long batOut) {
    const bf16* ih = ihG + (long)blockIdx.z * batIn;
    const bf16* il = ilG + (long)blockIdx.z * batIn;
    bf16* oh = ohG + (long)blockIdx.z * batOut;
    bf16* ol = olG + (long)blockIdx.z * batOut;
    int r0 = blockIdx.x * 32, c0 = blockIdx.y * 32;
    __shared__ bf16 th[32][33];
    __shared__ bf16 tl[32][33];
    int tx = threadIdx.x, ty = threadIdx.y;            // 32 x 8
    for (int rr = ty; rr < 32; rr += 8) {
        long idx = (long)(r0 + rr) * Ccols + c0 + tx;
        th[rr][tx] = ih[idx]; tl[rr][tx] = il[idx];
    }
    __syncthreads();
    for (int cc = ty; cc < 32; cc += 8) {
        long idx = (long)(c0 + cc) * R + r0 + tx;
        oh[idx] = th[tx][cc]; ol[idx] = tl[tx][cc];
    }
}

// ---------------- outputs ----------------------------------------------------
__global__ void out_templates_kernel(const float* __restrict__ t, float* __restrict__ out) {
    int b  = blockIdx.z;
    int d0 = blockIdx.x * 32, n0 = blockIdx.y * 32;
    __shared__ float tile[32][33];
    int tx = threadIdx.x, ty = threadIdx.y;
    const float* tb = t + ((long)b * NS + n0) * D_ + d0;
    for (int nn = ty; nn < 32; nn += 8)
        tile[nn][tx] = tb[(long)nn * D_ + tx];
    __syncthreads();
    float* ob = out + ((long)b * D_ + d0) * NS + n0;
    for (int dd = ty; dd < 32; dd += 8)
        ob[(long)dd * NS + tx] = tile[tx][dd];
}

__global__ void out_attn_kernel(const float* __restrict__ attn,
                                const float* __restrict__ colsum,
                                float* __restrict__ out) {
    int b  = blockIdx.z;
    int l0 = blockIdx.x * 32, n0 = blockIdx.y * 32;
    __shared__ float tile[32][33];
    __shared__ float sinv[32];
    int tx = threadIdx.x, ty = threadIdx.y;
    if (ty == 0) sinv[tx] = 1.0f / colsum[b * NS + n0 + tx];
    __syncthreads();
    const float* ab = attn + ((long)b * L_ + l0) * NS + n0;
    for (int ll = ty; ll < 32; ll += 8)
        tile[ll][tx] = ab[(long)ll * NS + tx] * sinv[tx];
    __syncthreads();
    float* ob = out + ((long)b * NS + n0) * L_ + l0;
    for (int nn = ty; nn < 32; nn += 8)
        ob[(long)nn * L_ + tx] = tile[tx][nn];
}

// ---------------- driver -----------------------------------------------------
extern "C" void kernel_launch(void* const* d_in, const int* in_sizes, int n_in,
                              void* d_out, int out_size) {
    const float* x       = (const float*)d_in[0];
    const float* tinit   = (const float*)d_in[1];
    const float* Wq      = (const float*)d_in[2];
    const float* Wk      = (const float*)d_in[3];
    const float* Wv      = (const float*)d_in[4];
    const float* ln_in_g = (const float*)d_in[5];
    const float* ln_in_b = (const float*)d_in[6];
    const float* ln_t_g  = (const float*)d_in[7];
    const float* ln_t_b  = (const float*)d_in[8];
    const float* ln_m_g  = (const float*)d_in[9];
    const float* ln_m_b  = (const float*)d_in[10];
    const float* W1      = (const float*)d_in[11];
    const float* b1      = (const float*)d_in[12];
    const float* W2      = (const float*)d_in[13];
    const float* b2      = (const float*)d_in[14];
    float* out = (float*)d_out;

    cudaFuncSetAttribute(hg_gemm<EPI_NONE>,           cudaFuncAttributeMaxDynamicSharedMemorySize, HG_SMEM);
    cudaFuncSetAttribute(hg_gemm<EPI_SPLIT>,          cudaFuncAttributeMaxDynamicSharedMemorySize, HG_SMEM);
    cudaFuncSetAttribute(hg_gemm<EPI_SPLIT_SCALE>,    cudaFuncAttributeMaxDynamicSharedMemorySize, HG_SMEM);
    cudaFuncSetAttribute(hg_gemm<EPI_SPLIT_BIAS_RELU>,cudaFuncAttributeMaxDynamicSharedMemorySize, HG_SMEM);
    cudaFuncSetAttribute(hg_gemm<EPI_ADD_BIAS>,       cudaFuncAttributeMaxDynamicSharedMemorySize, HG_SMEM);
    cudaFuncSetAttribute(hg_gemm<EPI_UPDATE>,         cudaFuncAttributeMaxDynamicSharedMemorySize, HG_SMEM);

    bf16 *xnh, *xnl, *kh, *kl, *vh, *vl, *vTh, *vTl;
    bf16 *WqTh, *WqTl, *WkTh, *WkTl, *WvTh, *WvTl, *W1Th, *W1Tl, *W2Th, *W2Tl;
    bf16 *tlnh, *tlnl, *qh, *ql, *aTh, *aTl, *hidh, *hidl;
    float *t, *attn, *colpart, *colsum;
    cudaGetSymbolAddress((void**)&xnh, g_xn_hi);   cudaGetSymbolAddress((void**)&xnl, g_xn_lo);
    cudaGetSymbolAddress((void**)&kh,  g_k_hi);    cudaGetSymbolAddress((void**)&kl,  g_k_lo);
    cudaGetSymbolAddress((void**)&vh,  g_v_hi);    cudaGetSymbolAddress((void**)&vl,  g_v_lo);
    cudaGetSymbolAddress((void**)&vTh, g_vT_hi);   cudaGetSymbolAddress((void**)&vTl, g_vT_lo);
    cudaGetSymbolAddress((void**)&WqTh, g_WqT_hi); cudaGetSymbolAddress((void**)&WqTl, g_WqT_lo);
    cudaGetSymbolAddress((void**)&WkTh, g_WkT_hi); cudaGetSymbolAddress((void**)&WkTl, g_WkT_lo);
    cudaGetSymbolAddress((void**)&WvTh, g_WvT_hi); cudaGetSymbolAddress((void**)&WvTl, g_WvT_lo);
    cudaGetSymbolAddress((void**)&W1Th, g_W1T_hi); cudaGetSymbolAddress((void**)&W1Tl, g_W1T_lo);
    cudaGetSymbolAddress((void**)&W2Th, g_W2T_hi); cudaGetSymbolAddress((void**)&W2Tl, g_W2T_lo);
    cudaGetSymbolAddress((void**)&tlnh, g_tln_hi); cudaGetSymbolAddress((void**)&tlnl, g_tln_lo);
    cudaGetSymbolAddress((void**)&qh,  g_q_hi);    cudaGetSymbolAddress((void**)&ql,  g_q_lo);
    cudaGetSymbolAddress((void**)&aTh, g_attnT_hi);cudaGetSymbolAddress((void**)&aTl, g_attnT_lo);
    cudaGetSymbolAddress((void**)&hidh, g_hid_hi); cudaGetSymbolAddress((void**)&hidl, g_hid_lo);
    cudaGetSymbolAddress((void**)&t,    g_t);
    cudaGetSymbolAddress((void**)&attn, g_attn);
    cudaGetSymbolAddress((void**)&colpart, g_colpart);
    cudaGetSymbolAddress((void**)&colsum,  g_colsum);

    const float scale = 0.03125f;  // 1024^-0.5
    dim3 tb32(32, 8);

    bcast_templates_kernel<<<8192, 256>>>(tinit, t);
    ln_transpose_kernel<<<dim3(L_ / 32, B_), tb32>>>(x, ln_in_g, ln_in_b, xnh, xnl);

    // weight transposes + splits (W [K,N] f32 -> WT [N,K] bf16 hi/lo)
    transpose_split_kernel<<<dim3(C_/32, D_/32, 1), tb32>>>(Wq, WqTh, WqTl, C_, D_, 0, 0);
    transpose_split_kernel<<<dim3(C_/32, D_/32, 1), tb32>>>(Wk, WkTh, WkTl, C_, D_, 0, 0);
    transpose_split_kernel<<<dim3(C_/32, D_/32, 1), tb32>>>(Wv, WvTh, WvTl, C_, D_, 0, 0);
    transpose_split_kernel<<<dim3(D_/32, MLPD/32, 1), tb32>>>(W1, W1Th, W1Tl, D_, MLPD, 0, 0);
    transpose_split_kernel<<<dim3(MLPD/32, D_/32, 1), tb32>>>(W2, W2Th, W2Tl, MLPD, D_, 0, 0);

    // k = xn @ Wk ; v = xn @ Wv  -> bf16 hi/lo
    hg_gemm<EPI_SPLIT><<<dim3(D_/128, (B_*L_)/128, 1), 256, HG_SMEM>>>(
        xnh, xnl, WkTh, WkTl, nullptr, nullptr, kh, kl, nullptr, nullptr,
        1.f, B_*L_, D_, C_, 0, 0, 0, 0);
    hg_gemm<EPI_SPLIT><<<dim3(D_/128, (B_*L_)/128, 1), 256, HG_SMEM>>>(
        xnh, xnl, WvTh, WvTl, nullptr, nullptr, vh, vl, nullptr, nullptr,
        1.f, B_*L_, D_, C_, 0, 0, 0, 0);
    // vT[b, d, l] = v[b, l, d]
    transpose_bf16_kernel<<<dim3(L_/32, D_/32, B_), tb32>>>(
        vh, vl, vTh, vTl, L_, D_, (long)L_*D_, (long)D_*L_);

    for (int it = 0; it < TIT; it++) {
        ln_rows_split_kernel<<<B_*NS, 256>>>(t, ln_t_g, ln_t_b, tlnh, tlnl);
        // q = LN(t) @ Wq * scale  -> bf16 hi/lo
        hg_gemm<EPI_SPLIT_SCALE><<<dim3(D_/128, (B_*NS)/128, 1), 256, HG_SMEM>>>(
            tlnh, tlnl, WqTh, WqTl, nullptr, nullptr, qh, ql, nullptr, nullptr,
            scale, B_*NS, D_, D_, 0, 0, 0, 0);
        // logits[b,l,n] = k[b,l,:] . q[b,n,:]
        hg_gemm<EPI_NONE><<<dim3(NS/128, L_/128, B_), 256, HG_SMEM>>>(
            kh, kl, qh, ql, attn, nullptr, nullptr, nullptr, nullptr, nullptr,
            1.f, L_, NS, D_, (long)L_*D_, (long)NS*D_, (long)L_*NS, 0);
        softmax_kernel<<<(B_*L_)/8, 256>>>(attn);
        colpart_kernel<<<dim3(32, B_), 256>>>(attn, colpart);
        colreduce_kernel<<<8, 256>>>(colpart, colsum);
        // attnT[b, n, l] = attn[b, l, n] (split)
        transpose_split_kernel<<<dim3(L_/32, NS/32, B_), tb32>>>(
            attn, aTh, aTl, L_, NS, (long)L_*NS, (long)NS*L_);
        // t[n,d] += sum_l attnT[n,l] * vT[d,l] / colsum[n]
        hg_gemm<EPI_UPDATE><<<dim3(D_/128, NS/128, B_), 256, HG_SMEM>>>(
            aTh, aTl, vTh, vTl, t, t, nullptr, nullptr, nullptr, colsum,
            1.f, NS, D_, L_, (long)NS*L_, (long)D_*L_, (long)NS*D_, NS);
        // MLP residual
        ln_rows_split_kernel<<<B_*NS, 256>>>(t, ln_m_g, ln_m_b, tlnh, tlnl);
        hg_gemm<EPI_SPLIT_BIAS_RELU><<<dim3(MLPD/128, (B_*NS)/128, 1), 256, HG_SMEM>>>(
            tlnh, tlnl, W1Th, W1Tl, nullptr, nullptr, hidh, hidl, b1, nullptr,
            1.f, B_*NS, MLPD, D_, 0, 0, 0, 0);
        hg_gemm<EPI_ADD_BIAS><<<dim3(D_/128, (B_*NS)/128, 1), 256, HG_SMEM>>>(
            hidh, hidl, W2Th, W2Tl, t, t, nullptr, nullptr, b2, nullptr,
            1.f, B_*NS, D_, MLPD, 0, 0, 0, 0);
    }

    out_templates_kernel<<<dim3(D_/32, NS/32, B_), tb32>>>(t, out);
    out_attn_kernel<<<dim3(L_/32, NS/32, B_), tb32>>>(
        attn, colsum, out + (long)B_ * D_ * NS);
}

// round 16
// speedup vs baseline: 1.5343x; 1.0089x over previous
#include <cuda_runtime.h>
#include <cuda_bf16.h>
#include <cstdint>

#define B_   8
#define L_   4096
#define C_   1024
#define D_   1024
#define NS   256
#define MLPD 512
#define TIT  6
#define LNEPS 1e-5f

typedef unsigned long long u64;
typedef __nv_bfloat16 bf16;

// ---------------- scratch (device globals; no allocations allowed) ----------
__device__ bf16  g_xn_hi[B_ * L_ * C_];
__device__ bf16  g_xn_lo[B_ * L_ * C_];
__device__ bf16  g_k_hi [B_ * L_ * D_];
__device__ bf16  g_k_lo [B_ * L_ * D_];
__device__ bf16  g_v_hi [B_ * L_ * D_];
__device__ bf16  g_v_lo [B_ * L_ * D_];
__device__ bf16  g_vT_hi[B_ * D_ * L_];
__device__ bf16  g_vT_lo[B_ * D_ * L_];
__device__ bf16  g_WqT_hi[D_ * D_],  g_WqT_lo[D_ * D_];
__device__ bf16  g_WkT_hi[D_ * C_],  g_WkT_lo[D_ * C_];
__device__ bf16  g_WvT_hi[D_ * C_],  g_WvT_lo[D_ * C_];
__device__ bf16  g_W1T_hi[MLPD * D_], g_W1T_lo[MLPD * D_];
__device__ bf16  g_W2T_hi[D_ * MLPD], g_W2T_lo[D_ * MLPD];
__device__ float g_t   [B_ * NS * D_];
__device__ bf16  g_tln_hi[B_ * NS * D_], g_tln_lo[B_ * NS * D_];
__device__ bf16  g_q_hi  [B_ * NS * D_], g_q_lo  [B_ * NS * D_];
__device__ float g_attn[B_ * L_ * NS];
__device__ bf16  g_attnT_hi[B_ * NS * L_], g_attnT_lo[B_ * NS * L_];
__device__ float g_colpart[32 * B_ * NS];
__device__ float g_colsum[B_ * NS];
__device__ bf16  g_hid_hi[B_ * NS * MLPD], g_hid_lo[B_ * NS * MLPD];
__device__ float g_upart[2 * B_ * NS * D_];   // split-K partials (16.8 MB)

// ---------------- helpers -----------------------------------------------------
__device__ __forceinline__ uint32_t smem_to_u32(const void* p) {
    uint32_t a;
    asm("{ .reg .u64 t; cvta.to.shared.u64 t, %1; cvt.u32.u64 %0, t; }"
        : "=r"(a) : "l"(p));
    return a;
}
__device__ __forceinline__ void cp16(uint32_t saddr, const void* g) {
    asm volatile("cp.async.cg.shared.global [%0], [%1], 16;" :: "r"(saddr), "l"(g));
}
#define CP_COMMIT() asm volatile("cp.async.commit_group;" ::: "memory")
#define CP_WAIT(N)  asm volatile("cp.async.wait_group %0;" :: "n"(N) : "memory")

__device__ __forceinline__ void ldm_x4(uint32_t &r0, uint32_t &r1, uint32_t &r2,
                                       uint32_t &r3, uint32_t addr) {
    asm volatile("ldmatrix.sync.aligned.m8n8.x4.shared.b16 {%0,%1,%2,%3}, [%4];"
                 : "=r"(r0), "=r"(r1), "=r"(r2), "=r"(r3) : "r"(addr));
}
__device__ __forceinline__ void mma_bf16(float* c, const uint32_t* a,
                                         uint32_t b0, uint32_t b1) {
    asm volatile("mma.sync.aligned.m16n8k16.row.col.f32.bf16.bf16.f32 "
                 "{%0,%1,%2,%3}, {%4,%5,%6,%7}, {%8,%9}, {%0,%1,%2,%3};"
                 : "+f"(c[0]), "+f"(c[1]), "+f"(c[2]), "+f"(c[3])
                 : "r"(a[0]), "r"(a[1]), "r"(a[2]), "r"(a[3]), "r"(b0), "r"(b1));
}
__device__ __forceinline__ void split_bf16(float x, bf16 &h, bf16 &l) {
    h = __float2bfloat16(x);
    l = __float2bfloat16(x - __bfloat162float(h));
}

// ---------------- HMMA GEMM: D[M,N] = A[M,K] . B[N,K]^T (bf16 hi/lo split) ---
// Block 128x128, BK=32, 8 warps (2m x 4n), warp tile 64x32, m16n8k16 frags.
// __launch_bounds__(256, 2): 2 CTAs/SM. Optional split-K via kslices
// (z encodes batch*kslices; slice offset = ks*K along rows of stride ldA/ldB).
enum { EPI_NONE = 0, EPI_SPLIT = 1, EPI_SPLIT_SCALE = 2,
       EPI_SPLIT_BIAS_RELU = 3, EPI_ADD_BIAS = 4 };

#define HG_SMEM 65536
#define STG 32768

// swizzled byte offset within one 128x(4x16B) matrix buffer
__device__ __forceinline__ uint32_t swz(int row, int ch) {
    return (uint32_t)(row * 64 + ((ch ^ ((row >> 1) & 3)) << 4));
}

template<int EPI>
__global__ void __launch_bounds__(256, 2)
hg_gemm(const bf16* __restrict__ AhiG, const bf16* __restrict__ AloG,
        const bf16* __restrict__ BhiG, const bf16* __restrict__ BloG,
        float* Cf32, const float* __restrict__ Cres,
        bf16* Chi, bf16* Clo, const float* __restrict__ biasg,
        float alpha, int M, int N, int K, int ldA, int ldB, int kslices,
        long batA, long batB, long batC) {
    extern __shared__ char smem[];
    const uint32_t sbase = smem_to_u32(smem);
    const int tid = threadIdx.x;
    const int wid = tid >> 5, lane = tid & 31;
    const int warp_m = wid & 1, warp_n = wid >> 1;
    const int m0 = blockIdx.y * 128;
    const int n0 = blockIdx.x * 128;
    const int z  = blockIdx.z;
    const int zb = z / kslices, ks = z - zb * kslices;

    const bf16* Ahi = AhiG + (long)zb * batA + (long)ks * K;
    const bf16* Alo = AloG + (long)zb * batA + (long)ks * K;
    const bf16* Bhi = BhiG + (long)zb * batB + (long)ks * K;
    const bf16* Blo = BloG + (long)zb * batB + (long)ks * K;
    float* Cw = Cf32 ? Cf32 + (long)z * batC : nullptr;
    const float* Cr = Cres ? Cres + (long)z * batC : nullptr;
    bf16* Ch = Chi ? Chi + (long)z * batC : nullptr;
    bf16* Cl = Clo ? Clo + (long)z * batC : nullptr;

    float acc[4][4][4];
    #pragma unroll
    for (int i = 0; i < 4; i++)
        #pragma unroll
        for (int j = 0; j < 4; j++)
            #pragma unroll
            for (int r = 0; r < 4; r++) acc[i][j][r] = 0.f;

    const int S = K / 32;

    // stage loader: 4 matrices x 128 rows x 4 chunks(16B) = 2048 cp.async
    auto load_stage = [&](int s) {
        const int p = s & 1;
        const int k0 = s * 32;
        const uint32_t sb = sbase + p * STG;
        #pragma unroll
        for (int i = 0; i < 8; i++) {
            int gi = i * 256 + tid;
            int mat = gi >> 9;
            int rem = gi & 511;
            int row = rem >> 2;
            int ch  = rem & 3;
            const bf16* src;
            if (mat == 0)      src = Ahi + (long)(m0 + row) * ldA + k0 + ch * 8;
            else if (mat == 1) src = Alo + (long)(m0 + row) * ldA + k0 + ch * 8;
            else if (mat == 2) src = Bhi + (long)(n0 + row) * ldB + k0 + ch * 8;
            else               src = Blo + (long)(n0 + row) * ldB + k0 + ch * 8;
            cp16(sb + mat * 8192 + swz(row, ch), src);
        }
        CP_COMMIT();
    };

    load_stage(0);

    for (int s = 0; s < S; s++) {
        const bool more = (s + 1 < S);
        if (more) load_stage(s + 1);
        if (more) { CP_WAIT(1); } else { CP_WAIT(0); }
        __syncthreads();

        const uint32_t sb = sbase + (s & 1) * STG;
        const int lr = lane & 7, lh = (lane >> 3) & 1, lc = (lane >> 4) & 1;

        #pragma unroll
        for (int kh = 0; kh < 2; kh++) {
            uint32_t ah[4][4], al[4][4];
            #pragma unroll
            for (int tm = 0; tm < 4; tm++) {
                int row = warp_m * 64 + tm * 16 + lr + lh * 8;
                int ch  = 2 * kh + lc;
                uint32_t off = swz(row, ch);
                ldm_x4(ah[tm][0], ah[tm][1], ah[tm][2], ah[tm][3], sb + off);
                ldm_x4(al[tm][0], al[tm][1], al[tm][2], al[tm][3], sb + 8192 + off);
            }
            #pragma unroll
            for (int tnp = 0; tnp < 2; tnp++) {
                int row = warp_n * 32 + tnp * 16 + lr + lh * 8;
                int ch  = 2 * kh + lc;
                uint32_t off = swz(row, ch);
                uint32_t bh0, bh1, bh2, bh3, bl0, bl1, bl2, bl3;
                ldm_x4(bh0, bh1, bh2, bh3, sb + 16384 + off);
                ldm_x4(bl0, bl1, bl2, bl3, sb + 24576 + off);
                #pragma unroll
                for (int tm = 0; tm < 4; tm++) {
                    mma_bf16(acc[tm][2*tnp],   ah[tm], bh0, bh2);
                    mma_bf16(acc[tm][2*tnp+1], ah[tm], bh1, bh3);
                    mma_bf16(acc[tm][2*tnp],   ah[tm], bl0, bl2);
                    mma_bf16(acc[tm][2*tnp+1], ah[tm], bl1, bl3);
                    mma_bf16(acc[tm][2*tnp],   al[tm], bh0, bh2);
                    mma_bf16(acc[tm][2*tnp+1], al[tm], bh1, bh3);
                }
            }
        }
        __syncthreads();
    }

    #pragma unroll
    for (int tm = 0; tm < 4; tm++) {
        #pragma unroll
        for (int tn = 0; tn < 4; tn++) {
            float* c = acc[tm][tn];
            int row = m0 + warp_m * 64 + tm * 16 + (lane >> 2);
            int col = n0 + warp_n * 32 + tn * 8 + 2 * (lane & 3);
            #pragma unroll
            for (int h = 0; h < 2; h++) {
                int rw = row + h * 8;
                float v0 = c[2*h], v1 = c[2*h+1];
                long idx = (long)rw * N + col;
                if (EPI == EPI_NONE) {
                    *(float2*)(Cw + idx) = make_float2(v0, v1);
                } else if (EPI == EPI_SPLIT || EPI == EPI_SPLIT_SCALE ||
                           EPI == EPI_SPLIT_BIAS_RELU) {
                    if (EPI == EPI_SPLIT_SCALE) { v0 *= alpha; v1 *= alpha; }
                    if (EPI == EPI_SPLIT_BIAS_RELU) {
                        v0 = fmaxf(v0 + biasg[col], 0.f);
                        v1 = fmaxf(v1 + biasg[col + 1], 0.f);
                    }
                    bf16 h0, l0, h1, l1;
                    split_bf16(v0, h0, l0); split_bf16(v1, h1, l1);
                    __nv_bfloat162 ph; ph.x = h0; ph.y = h1;
                    __nv_bfloat162 pl; pl.x = l0; pl.y = l1;
                    *(__nv_bfloat162*)(Ch + idx) = ph;
                    *(__nv_bfloat162*)(Cl + idx) = pl;
                } else if (EPI == EPI_ADD_BIAS) {
                    float2 r = *(const float2*)(Cr + idx);
                    *(float2*)(Cw + idx) =
                        make_float2(r.x + v0 + biasg[col], r.y + v1 + biasg[col + 1]);
                }
            }
        }
    }
}

// ---------------- fused softmax + column partials + transposed hi/lo split ---
// Grid (L/128, B). Block 256 threads. Two-pass over logits in g_attn:
// pass 1: per-row max & inv-sum; pass 2 (4 chunks of 64 n):
// recompute p = exp(v-max)*inv + 1e-8, stage [64 n][128 l] in smem, write
// attnT hi/lo (16B vectorized), accumulate column partials. attn f32 p-values
// are written back only when writeAttn != 0 (final iteration).
__global__ void __launch_bounds__(256)
softmax_fuse_kernel(float* __restrict__ attn,
                    bf16* __restrict__ aTh, bf16* __restrict__ aTl,
                    float* __restrict__ colpart, int writeAttn) {
    __shared__ float smax[128], sinv[128];
    __shared__ float stile[64][132];
    __shared__ float cq[64][4];
    const int tid = threadIdx.x, wid = tid >> 5, lane = tid & 31;
    const int l0 = blockIdx.x * 128, b = blockIdx.y;
    float* base = attn + ((long)b * L_ + l0) * NS;

    // pass 1: row max + inv sum
    for (int r = 0; r < 16; r++) {
        int row = wid * 16 + r;
        const float4* p = (const float4*)(base + (long)row * NS);
        float4 a = p[lane], c = p[lane + 32];
        float m = fmaxf(fmaxf(fmaxf(a.x, a.y), fmaxf(a.z, a.w)),
                        fmaxf(fmaxf(c.x, c.y), fmaxf(c.z, c.w)));
        #pragma unroll
        for (int o = 16; o > 0; o >>= 1) m = fmaxf(m, __shfl_xor_sync(0xffffffffu, m, o));
        float s = __expf(a.x - m) + __expf(a.y - m) + __expf(a.z - m) + __expf(a.w - m)
                + __expf(c.x - m) + __expf(c.y - m) + __expf(c.z - m) + __expf(c.w - m);
        #pragma unroll
        for (int o = 16; o > 0; o >>= 1) s += __shfl_xor_sync(0xffffffffu, s, o);
        if (lane == 0) { smax[row] = m; sinv[row] = 1.0f / s; }
    }
    __syncthreads();

    // pass 2: 4 chunks of 64 columns
    for (int nc = 0; nc < 4; nc++) {
        for (int r = 0; r < 16; r++) {
            int row = wid * 16 + r;
            float2 v = *(const float2*)(base + (long)row * NS + nc * 64 + lane * 2);
            float m = smax[row], inv = sinv[row];
            float p0 = __expf(v.x - m) * inv + 1e-8f;
            float p1 = __expf(v.y - m) * inv + 1e-8f;
            stile[lane * 2][row]     = p0;
            stile[lane * 2 + 1][row] = p1;
            if (writeAttn)
                *(float2*)(base + (long)row * NS + nc * 64 + lane * 2) = make_float2(p0, p1);
        }
        __syncthreads();
        // write transposed hi/lo + column partial quarters
        {
            int nl = tid >> 2, qd = tid & 3;          // n-local 0..63, l-quarter 0..3
            float csum = 0.f;
            union { uint4 u[2]; __nv_bfloat162 p[8]; } hb, lb;
            #pragma unroll
            for (int i = 0; i < 16; i++) {
                float v0 = stile[nl][qd * 32 + 2 * i];
                float v1 = stile[nl][qd * 32 + 2 * i + 1];
                csum += v0 + v1;
                bf16 h0, o0, h1, o1;
                split_bf16(v0, h0, o0); split_bf16(v1, h1, o1);
                __nv_bfloat162 ph; ph.x = h0; ph.y = h1;
                __nv_bfloat162 pl; pl.x = o0; pl.y = o1;
                if (i < 8) { hb.p[i] = ph; lb.p[i] = pl; }
                else {
                    // flush first 8 pairs once, then reuse
                    if (i == 8) {
                        long ob = ((long)b * NS + nc * 64 + nl) * L_ + l0 + qd * 32;
                        *(uint4*)(aTh + ob)     = hb.u[0];
                        *(uint4*)(aTh + ob + 8) = hb.u[1];
                        *(uint4*)(aTl + ob)     = lb.u[0];
                        *(uint4*)(aTl + ob + 8) = lb.u[1];
                    }
                    hb.p[i - 8] = ph; lb.p[i - 8] = pl;
                }
            }
            long ob = ((long)b * NS + nc * 64 + nl) * L_ + l0 + qd * 32 + 16;
            *(uint4*)(aTh + ob)     = hb.u[0];
            *(uint4*)(aTh + ob + 8) = hb.u[1];
            *(uint4*)(aTl + ob)     = lb.u[0];
            *(uint4*)(aTl + ob + 8) = lb.u[1];
            cq[nl][qd] = csum;
        }
        __syncthreads();
        if (tid < 64) {
            float s = cq[tid][0] + cq[tid][1] + cq[tid][2] + cq[tid][3];
            colpart[(long)blockIdx.x * B_ * NS + b * NS + nc * 64 + tid] = s;
        }
        __syncthreads();
    }
}

// ---------------- split-K(2) reduce for the update GEMM -----------------------
__global__ void update_reduce_kernel(const float* __restrict__ part,
                                     const float* __restrict__ colsum,
                                     float* __restrict__ t) {
    int row = blockIdx.x;              // b*NS + n
    int tid = threadIdx.x;             // 256
    float inv = 1.0f / colsum[row];
    int b = row >> 8, n = row & 255;
    const float4* q0 = (const float4*)(part + ((long)(b * 2 + 0) * NS + n) * D_);
    const float4* q1 = (const float4*)(part + ((long)(b * 2 + 1) * NS + n) * D_);
    float4* tp = (float4*)(t + (long)row * D_);
    float4 a = q0[tid], c = q1[tid], o = tp[tid];
    o.x += (a.x + c.x) * inv;
    o.y += (a.y + c.y) * inv;
    o.z += (a.z + c.z) * inv;
    o.w += (a.w + c.w) * inv;
    tp[tid] = o;
}

// ---------------- elementwise kernels ----------------------------------------
__global__ void bcast_templates_kernel(const float* __restrict__ tinit,
                                       float* __restrict__ t) {
    int idx = blockIdx.x * blockDim.x + threadIdx.x;
    t[idx] = tinit[idx & (NS * D_ - 1)];
}

// LN over channels + transpose: x[B,C,L] -> xn hi/lo [B,L,C]
__global__ void ln_transpose_kernel(const float* __restrict__ x,
                                    const float* __restrict__ g,
                                    const float* __restrict__ bt,
                                    bf16* __restrict__ xh, bf16* __restrict__ xl) {
    int b  = blockIdx.y;
    int l0 = blockIdx.x * 32;
    int tx = threadIdx.x, ty = threadIdx.y;           // 32 x 8
    __shared__ float ssum[8][32];
    __shared__ float ssq [8][32];
    __shared__ float smean[32], srstd[32];
    const float* xb = x + (long)b * C_ * L_;
    float s = 0.f, q = 0.f;
    for (int c = ty; c < C_; c += 8) {
        float v = xb[(long)c * L_ + l0 + tx];
        s += v; q += v * v;
    }
    ssum[ty][tx] = s; ssq[ty][tx] = q;
    __syncthreads();
    if (ty == 0) {
        float ts = 0.f, tq = 0.f;
        #pragma unroll
        for (int i = 0; i < 8; i++) { ts += ssum[i][tx]; tq += ssq[i][tx]; }
        float mean = ts * (1.0f / C_);
        float var  = tq * (1.0f / C_) - mean * mean;
        smean[tx] = mean;
        srstd[tx] = rsqrtf(var + LNEPS);
    }
    __syncthreads();
    __shared__ float tile[32][33];
    long outb = ((long)b * L_ + l0) * C_;
    for (int c0 = 0; c0 < C_; c0 += 32) {
        __syncthreads();
        for (int cc = ty; cc < 32; cc += 8) {
            float v = xb[(long)(c0 + cc) * L_ + l0 + tx];
            tile[cc][tx] = (v - smean[tx]) * srstd[tx];
        }
        __syncthreads();
        for (int ll = ty; ll < 32; ll += 8) {
            int c = c0 + tx;
            float v = tile[tx][ll] * g[c] + bt[c];
            bf16 h, l; split_bf16(v, h, l);
            long idx = outb + (long)ll * C_ + c;
            xh[idx] = h; xl[idx] = l;
        }
    }
}

// LN over rows of [rows, 1024], split output
__global__ void ln_rows_split_kernel(const float* __restrict__ in,
                                     const float* __restrict__ g,
                                     const float* __restrict__ bt,
                                     bf16* __restrict__ oh, bf16* __restrict__ ol) {
    int row = blockIdx.x;
    int tid = threadIdx.x;                             // 256
    const float4* pin = (const float4*)(in + (long)row * D_);
    float4 v = pin[tid];
    float s = v.x + v.y + v.z + v.w;
    float q = v.x*v.x + v.y*v.y + v.z*v.z + v.w*v.w;
    #pragma unroll
    for (int o = 16; o > 0; o >>= 1) {
        s += __shfl_down_sync(0xffffffffu, s, o);
        q += __shfl_down_sync(0xffffffffu, q, o);
    }
    __shared__ float ws[8], wq[8];
    __shared__ float smn, srs;
    int warp = tid >> 5, lane = tid & 31;
    if (lane == 0) { ws[warp] = s; wq[warp] = q; }
    __syncthreads();
    if (tid == 0) {
        float ts = 0.f, tq = 0.f;
        #pragma unroll
        for (int i = 0; i < 8; i++) { ts += ws[i]; tq += wq[i]; }
        float mean = ts * (1.0f / D_);
        float var  = tq * (1.0f / D_) - mean * mean;
        smn = mean; srs = rsqrtf(var + LNEPS);
    }
    __syncthreads();
    float mean = smn, rstd = srs;
    float4 gg = ((const float4*)g)[tid];
    float4 bb = ((const float4*)bt)[tid];
    float o0 = (v.x - mean) * rstd * gg.x + bb.x;
    float o1 = (v.y - mean) * rstd * gg.y + bb.y;
    float o2 = (v.z - mean) * rstd * gg.z + bb.z;
    float o3 = (v.w - mean) * rstd * gg.w + bb.w;
    bf16 h0,l0,h1,l1,h2,l2,h3,l3;
    split_bf16(o0,h0,l0); split_bf16(o1,h1,l1);
    split_bf16(o2,h2,l2); split_bf16(o3,h3,l3);
    __nv_bfloat162* ph = (__nv_bfloat162*)(oh + (long)row * D_);
    __nv_bfloat162* pl = (__nv_bfloat162*)(ol + (long)row * D_);
    __nv_bfloat162 a; a.x=h0; a.y=h1; ph[tid*2]=a; a.x=h2; a.y=h3; ph[tid*2+1]=a;
    __nv_bfloat162 c; c.x=l0; c.y=l1; pl[tid*2]=c; c.x=l2; c.y=l3; pl[tid*2+1]=c;
}

__global__ void colreduce_kernel(const float* __restrict__ part,
                                 float* __restrict__ colsum) {
    int idx = blockIdx.x * blockDim.x + threadIdx.x;
    float s = 0.f;
    #pragma unroll
    for (int c = 0; c < 32; c++) s += part[(long)c * B_ * NS + idx];
    colsum[idx] = s;
}

// transpose + split: in f32 [R, Ccols] -> out hi/lo bf16 [Ccols, R]  (batched)
__global__ void transpose_split_kernel(const float* __restrict__ inG,
                                       bf16* __restrict__ ohG, bf16* __restrict__ olG,
                                       int R, int Ccols, long batIn, long batOut) {
    const float* in = inG + (long)blockIdx.z * batIn;
    bf16* oh = ohG + (long)blockIdx.z * batOut;
    bf16* ol = olG + (long)blockIdx.z * batOut;
    int r0 = blockIdx.x * 32, c0 = blockIdx.y * 32;
    __shared__ float tile[32][33];
    int tx = threadIdx.x, ty = threadIdx.y;            // 32 x 8
    for (int rr = ty; rr < 32; rr += 8)
        tile[rr][tx] = in[(long)(r0 + rr) * Ccols + c0 + tx];
    __syncthreads();
    for (int cc = ty; cc < 32; cc += 8) {
        float v = tile[tx][cc];
        bf16 h, l; split_bf16(v, h, l);
        long idx = (long)(c0 + cc) * R + r0 + tx;
        oh[idx] = h; ol[idx] = l;
    }
}

// transpose bf16 pair: in hi/lo [R, Ccols] -> out hi/lo [Ccols, R]  (batched)
__global__ void transpose_bf16_kernel(const bf16* __restrict__ ihG, const bf16* __restrict__ ilG,
                                      bf16* __restrict__ ohG, bf16* __restrict__ olG,
                                      int R, int Ccols, long batIn, long batOut) {
    const bf16* ih = ihG + (long)blockIdx.z * batIn;
    const bf16* il = ilG + (long)blockIdx.z * batIn;
    bf16* oh = ohG + (long)blockIdx.z * batOut;
    bf16* ol = olG + (long)blockIdx.z * batOut;
    int r0 = blockIdx.x * 32, c0 = blockIdx.y * 32;
    __shared__ bf16 th[32][33];
    __shared__ bf16 tl[32][33];
    int tx = threadIdx.x, ty = threadIdx.y;            // 32 x 8
    for (int rr = ty; rr < 32; rr += 8) {
        long idx = (long)(r0 + rr) * Ccols + c0 + tx;
        th[rr][tx] = ih[idx]; tl[rr][tx] = il[idx];
    }
    __syncthreads();
    for (int cc = ty; cc < 32; cc += 8) {
        long idx = (long)(c0 + cc) * R + r0 + tx;
        oh[idx] = th[tx][cc]; ol[idx] = tl[tx][cc];
    }
}

// ---------------- outputs ----------------------------------------------------
__global__ void out_templates_kernel(const float* __restrict__ t, float* __restrict__ out) {
    int b  = blockIdx.z;
    int d0 = blockIdx.x * 32, n0 = blockIdx.y * 32;
    __shared__ float tile[32][33];
    int tx = threadIdx.x, ty = threadIdx.y;
    const float* tb = t + ((long)b * NS + n0) * D_ + d0;
    for (int nn = ty; nn < 32; nn += 8)
        tile[nn][tx] = tb[(long)nn * D_ + tx];
    __syncthreads();
    float* ob = out + ((long)b * D_ + d0) * NS + n0;
    for (int dd = ty; dd < 32; dd += 8)
        ob[(long)dd * NS + tx] = tile[tx][dd];
}

__global__ void out_attn_kernel(const float* __restrict__ attn,
                                const float* __restrict__ colsum,
                                float* __restrict__ out) {
    int b  = blockIdx.z;
    int l0 = blockIdx.x * 32, n0 = blockIdx.y * 32;
    __shared__ float tile[32][33];
    __shared__ float sinv[32];
    int tx = threadIdx.x, ty = threadIdx.y;
    if (ty == 0) sinv[tx] = 1.0f / colsum[b * NS + n0 + tx];
    __syncthreads();
    const float* ab = attn + ((long)b * L_ + l0) * NS + n0;
    for (int ll = ty; ll < 32; ll += 8)
        tile[ll][tx] = ab[(long)ll * NS + tx] * sinv[tx];
    __syncthreads();
    float* ob = out + ((long)b * NS + n0) * L_ + l0;
    for (int nn = ty; nn < 32; nn += 8)
        ob[(long)nn * L_ + tx] = tile[tx][nn];
}

// ---------------- driver -----------------------------------------------------
extern "C" void kernel_launch(void* const* d_in, const int* in_sizes, int n_in,
                              void* d_out, int out_size) {
    const float* x       = (const float*)d_in[0];
    const float* tinit   = (const float*)d_in[1];
    const float* Wq      = (const float*)d_in[2];
    const float* Wk      = (const float*)d_in[3];
    const float* Wv      = (const float*)d_in[4];
    const float* ln_in_g = (const float*)d_in[5];
    const float* ln_in_b = (const float*)d_in[6];
    const float* ln_t_g  = (const float*)d_in[7];
    const float* ln_t_b  = (const float*)d_in[8];
    const float* ln_m_g  = (const float*)d_in[9];
    const float* ln_m_b  = (const float*)d_in[10];
    const float* W1      = (const float*)d_in[11];
    const float* b1      = (const float*)d_in[12];
    const float* W2      = (const float*)d_in[13];
    const float* b2      = (const float*)d_in[14];
    float* out = (float*)d_out;

    cudaFuncSetAttribute(hg_gemm<EPI_NONE>,           cudaFuncAttributeMaxDynamicSharedMemorySize, HG_SMEM);
    cudaFuncSetAttribute(hg_gemm<EPI_SPLIT>,          cudaFuncAttributeMaxDynamicSharedMemorySize, HG_SMEM);
    cudaFuncSetAttribute(hg_gemm<EPI_SPLIT_SCALE>,    cudaFuncAttributeMaxDynamicSharedMemorySize, HG_SMEM);
    cudaFuncSetAttribute(hg_gemm<EPI_SPLIT_BIAS_RELU>,cudaFuncAttributeMaxDynamicSharedMemorySize, HG_SMEM);
    cudaFuncSetAttribute(hg_gemm<EPI_ADD_BIAS>,       cudaFuncAttributeMaxDynamicSharedMemorySize, HG_SMEM);

    bf16 *xnh, *xnl, *kh, *kl, *vh, *vl, *vTh, *vTl;
    bf16 *WqTh, *WqTl, *WkTh, *WkTl, *WvTh, *WvTl, *W1Th, *W1Tl, *W2Th, *W2Tl;
    bf16 *tlnh, *tlnl, *qh, *ql, *aTh, *aTl, *hidh, *hidl;
    float *t, *attn, *colpart, *colsum, *upart;
    cudaGetSymbolAddress((void**)&xnh, g_xn_hi);   cudaGetSymbolAddress((void**)&xnl, g_xn_lo);
    cudaGetSymbolAddress((void**)&kh,  g_k_hi);    cudaGetSymbolAddress((void**)&kl,  g_k_lo);
    cudaGetSymbolAddress((void**)&vh,  g_v_hi);    cudaGetSymbolAddress((void**)&vl,  g_v_lo);
    cudaGetSymbolAddress((void**)&vTh, g_vT_hi);   cudaGetSymbolAddress((void**)&vTl, g_vT_lo);
    cudaGetSymbolAddress((void**)&WqTh, g_WqT_hi); cudaGetSymbolAddress((void**)&WqTl, g_WqT_lo);
    cudaGetSymbolAddress((void**)&WkTh, g_WkT_hi); cudaGetSymbolAddress((void**)&WkTl, g_WkT_lo);
    cudaGetSymbolAddress((void**)&WvTh, g_WvT_hi); cudaGetSymbolAddress((void**)&WvTl, g_WvT_lo);
    cudaGetSymbolAddress((void**)&W1Th, g_W1T_hi); cudaGetSymbolAddress((void**)&W1Tl, g_W1T_lo);
    cudaGetSymbolAddress((void**)&W2Th, g_W2T_hi); cudaGetSymbolAddress((void**)&W2Tl, g_W2T_lo);
    cudaGetSymbolAddress((void**)&tlnh, g_tln_hi); cudaGetSymbolAddress((void**)&tlnl, g_tln_lo);
    cudaGetSymbolAddress((void**)&qh,  g_q_hi);    cudaGetSymbolAddress((void**)&ql,  g_q_lo);
    cudaGetSymbolAddress((void**)&aTh, g_attnT_hi);cudaGetSymbolAddress((void**)&aTl, g_attnT_lo);
    cudaGetSymbolAddress((void**)&hidh, g_hid_hi); cudaGetSymbolAddress((void**)&hidl, g_hid_lo);
    cudaGetSymbolAddress((void**)&t,    g_t);
    cudaGetSymbolAddress((void**)&attn, g_attn);
    cudaGetSymbolAddress((void**)&colpart, g_colpart);
    cudaGetSymbolAddress((void**)&colsum,  g_colsum);
    cudaGetSymbolAddress((void**)&upart,   g_upart);

    const float scale = 0.03125f;  // 1024^-0.5
    dim3 tb32(32, 8);

    bcast_templates_kernel<<<8192, 256>>>(tinit, t);
    ln_transpose_kernel<<<dim3(L_ / 32, B_), tb32>>>(x, ln_in_g, ln_in_b, xnh, xnl);

    // weight transposes + splits (W [K,N] f32 -> WT [N,K] bf16 hi/lo)
    transpose_split_kernel<<<dim3(C_/32, D_/32, 1), tb32>>>(Wq, WqTh, WqTl, C_, D_, 0, 0);
    transpose_split_kernel<<<dim3(C_/32, D_/32, 1), tb32>>>(Wk, WkTh, WkTl, C_, D_, 0, 0);
    transpose_split_kernel<<<dim3(C_/32, D_/32, 1), tb32>>>(Wv, WvTh, WvTl, C_, D_, 0, 0);
    transpose_split_kernel<<<dim3(D_/32, MLPD/32, 1), tb32>>>(W1, W1Th, W1Tl, D_, MLPD, 0, 0);
    transpose_split_kernel<<<dim3(MLPD/32, D_/32, 1), tb32>>>(W2, W2Th, W2Tl, MLPD, D_, 0, 0);

    // k = xn @ Wk ; v = xn @ Wv  -> bf16 hi/lo
    hg_gemm<EPI_SPLIT><<<dim3(D_/128, (B_*L_)/128, 1), 256, HG_SMEM>>>(
        xnh, xnl, WkTh, WkTl, nullptr, nullptr, kh, kl, nullptr,
        1.f, B_*L_, D_, C_, C_, C_, 1, 0, 0, 0);
    hg_gemm<EPI_SPLIT><<<dim3(D_/128, (B_*L_)/128, 1), 256, HG_SMEM>>>(
        xnh, xnl, WvTh, WvTl, nullptr, nullptr, vh, vl, nullptr,
        1.f, B_*L_, D_, C_, C_, C_, 1, 0, 0, 0);
    // vT[b, d, l] = v[b, l, d]
    transpose_bf16_kernel<<<dim3(L_/32, D_/32, B_), tb32>>>(
        vh, vl, vTh, vTl, L_, D_, (long)L_*D_, (long)D_*L_);

    for (int it = 0; it < TIT; it++) {
        ln_rows_split_kernel<<<B_*NS, 256>>>(t, ln_t_g, ln_t_b, tlnh, tlnl);
        // q = LN(t) @ Wq * scale  -> bf16 hi/lo
        hg_gemm<EPI_SPLIT_SCALE><<<dim3(D_/128, (B_*NS)/128, 1), 256, HG_SMEM>>>(
            tlnh, tlnl, WqTh, WqTl, nullptr, nullptr, qh, ql, nullptr,
            scale, B_*NS, D_, D_, D_, D_, 1, 0, 0, 0);
        // logits[b,l,n] = k[b,l,:] . q[b,n,:]
        hg_gemm<EPI_NONE><<<dim3(NS/128, L_/128, B_), 256, HG_SMEM>>>(
            kh, kl, qh, ql, attn, nullptr, nullptr, nullptr, nullptr,
            1.f, L_, NS, D_, D_, D_, 1, (long)L_*D_, (long)NS*D_, (long)L_*NS);
        // fused softmax + col partials + transposed hi/lo split
        softmax_fuse_kernel<<<dim3(L_/128, B_), 256>>>(
            attn, aTh, aTl, colpart, it == TIT - 1 ? 1 : 0);
        colreduce_kernel<<<8, 256>>>(colpart, colsum);
        // update partials: split-K x2 over L -> 256 CTAs in one launch
        hg_gemm<EPI_NONE><<<dim3(D_/128, NS/128, B_*2), 256, HG_SMEM>>>(
            aTh, aTl, vTh, vTl, upart, nullptr, nullptr, nullptr, nullptr,
            1.f, NS, D_, L_/2, L_, L_, 2, (long)NS*L_, (long)D_*L_, (long)NS*D_);
        update_reduce_kernel<<<B_*NS, 256>>>(upart, colsum, t);
        // MLP residual
        ln_rows_split_kernel<<<B_*NS, 256>>>(t, ln_m_g, ln_m_b, tlnh, tlnl);
        hg_gemm<EPI_SPLIT_BIAS_RELU><<<dim3(MLPD/128, (B_*NS)/128, 1), 256, HG_SMEM>>>(
            tlnh, tlnl, W1Th, W1Tl, nullptr, nullptr, hidh, hidl, b1,
            1.f, B_*NS, MLPD, D_, D_, D_, 1, 0, 0, 0);
        hg_gemm<EPI_ADD_BIAS><<<dim3(D_/128, (B_*NS)/128, 1), 256, HG_SMEM>>>(
            hidh, hidl, W2Th, W2Tl, t, t, nullptr, nullptr, b2,
            1.f, B_*NS, D_, MLPD, MLPD, MLPD, 1, 0, 0, 0);
    }

    out_templates_kernel<<<dim3(D_/32, NS/32, B_), tb32>>>(t, out);
    out_attn_kernel<<<dim3(L_/32, NS/32, B_), tb32>>>(
        attn, colsum, out + (long)B_ * D_ * NS);
}